// round 10
// baseline (speedup 1.0000x reference)
#include <cuda_runtime.h>
#include <cuda_fp16.h>
#include <math.h>
#include <stdint.h>

#define NB 32
#define HW 1024

#define CKC 169   // x_ul_b channels
#define CQC 166   // ul_b channels
#define COC 160   // ul channels
#define KDIM 16
#define VDIM 80

// ---------------- scratch (static device memory; no allocations) ----------------
__device__ float g_cat  [(size_t)NB * CKC * HW];   // x_ul_b [n,169,1024]; ul_b = view +3*HW
__device__ float g_h    [(size_t)NB * CKC * HW];   // hidden A (K, Q, O chains)
__device__ float g_h2   [(size_t)NB * CKC * HW];   // hidden B (V), later Q gout
__device__ float g_big  [(size_t)NB * 2 * CKC * HW]; // stage-2 raw [2C, hw]
__device__ float g_gout [(size_t)NB * CKC * HW];   // K gout
__device__ float g_gout2[(size_t)NB * CKC * HW];   // V gout
__device__ float g_keys[(size_t)NB * KDIM * HW];
__device__ float g_quer[(size_t)NB * KDIM * HW];
__device__ float g_vals[(size_t)NB * VDIM * HW];
__device__ float g_att [(size_t)NB * HW * HW];
__device__ float g_attv[(size_t)NB * VDIM * HW];

__device__ __forceinline__ float eluf(float v) { return v > 0.f ? v : (expf(v) - 1.f); }

__device__ __forceinline__ void mma_f16(float* d, const unsigned* a, const unsigned* b) {
    asm volatile(
        "mma.sync.aligned.m16n8k16.row.col.f32.f16.f16.f32 "
        "{%0,%1,%2,%3}, {%4,%5,%6,%7}, {%8,%9}, {%0,%1,%2,%3};"
        : "+f"(d[0]), "+f"(d[1]), "+f"(d[2]), "+f"(d[3])
        : "r"(a[0]), "r"(a[1]), "r"(a[2]), "r"(a[3]), "r"(b[0]), "r"(b[1]));
}

// ---------------- concat inputs into [n,169,hw] ----------------
__global__ void build_cat_kernel(const float* __restrict__ x, const float* __restrict__ ul,
                                 const float* __restrict__ b, float* __restrict__ cat) {
    long idx = (long)blockIdx.x * blockDim.x + threadIdx.x;
    const long total = (long)NB * CKC * HW;
    if (idx >= total) return;
    int p = (int)(idx % HW);
    int c = (int)((idx / HW) % CKC);
    int n = (int)(idx / ((long)CKC * HW));
    float v;
    if (c < 3)        v = x [((long)n * 3   + c        ) * HW + p];
    else if (c < 163) v = ul[((long)n * 160 + (c - 3)  ) * HW + p];
    else              v = b [((long)n * 6   + (c - 163)) * HW + p];
    cat[idx] = v;
}

#define SAH 34   // smem stride in halves

// ============ FP16 MMA GEMM: Out = W*concat_elu(X) [+ W2*concat_elu(X2)] + bias[+bias2] ============
// Optional row-split (WB != null): rows >= Msplit use WB/biasB and write OutB (K+V fusion).
// CTA 64 out x 128 px, 256 threads = 8 warps (2 M x 4 N), warp tile 32x32, ping-pong smem.

#define MG_LOAD_CHUNK(kk)                                                              \
    {                                                                                  \
        const float* Xs; const float* Ws; int Ci; long xs; int fb;                     \
        if ((kk) < nk1) { Xs = X;  Ws = W;  Ci = Cin;  xs = xStride;  fb = (kk) * 32; } \
        else            { Xs = X2; Ws = W2; Ci = Cin2; xs = x2Stride; fb = ((kk) - nk1) * 32; } \
        const int lim = 2 * Ci;                                                        \
        const int o = o0 + arow;                                                       \
        const bool oOK = o < Cout;                                                     \
        const float* Wbase = Ws; long rowi = o;                                        \
        if (WB && o >= Msplit) { Wbase = WB; rowi = o - Msplit; }                      \
        _Pragma("unroll")                                                              \
        for (int jj = 0; jj < 4; ++jj) {                                               \
            const int f = fb + afs + 2 * jj;                                           \
            float2 w2 = {0.f, 0.f};                                                    \
            if (oOK && f < lim)                                                        \
                w2 = *reinterpret_cast<const float2*>(&Wbase[rowi * lim + f]);         \
            areg[2 * jj] = w2.x; areg[2 * jj + 1] = w2.y;                              \
        }                                                                              \
        const float* Xn = Xs + (long)n * xs;                                           \
        _Pragma("unroll")                                                              \
        for (int j = 0; j < 16; ++j) {                                                 \
            const int ff = fb + bf0 + j;                                               \
            float v = 0.f;                                                             \
            if (ff < lim) {                                                            \
                const int c  = (ff < Ci) ? ff : (ff - Ci);                             \
                const float xv = Xn[(long)c * HW + p0 + bpx];                          \
                v = (ff < Ci) ? eluf(xv) : eluf(-xv);                                  \
            }                                                                          \
            breg[j] = v;                                                               \
        }                                                                              \
    }

#define MG_STORE_CHUNK(buf)                                                            \
    {                                                                                  \
        __half* pa = &sA[buf][arow * SAH + afs];                                       \
        _Pragma("unroll")                                                              \
        for (int jj = 0; jj < 4; ++jj)                                                 \
            *reinterpret_cast<__half2*>(pa + 2 * jj) =                                 \
                __floats2half2_rn(areg[2 * jj], areg[2 * jj + 1]);                     \
        __half* pb = &sB[buf][bpx * SAH + bf0];                                        \
        _Pragma("unroll")                                                              \
        for (int jj = 0; jj < 8; ++jj)                                                 \
            *reinterpret_cast<__half2*>(pb + 2 * jj) =                                 \
                __floats2half2_rn(breg[2 * jj], breg[2 * jj + 1]);                     \
    }

#define MG_EPI_WRITE(oo, v0, v1, pp) do {                                              \
    const int _o = (oo);                                                               \
    if (_o < Cout) {                                                                   \
        float bo_; float* dst;                                                         \
        if (WB && _o >= Msplit) {                                                      \
            bo_ = biasB[_o - Msplit];                                                  \
            dst = OutB + (long)n * oStrideB + (long)(_o - Msplit) * HW + (pp);         \
        } else {                                                                       \
            bo_ = bias[_o] + (bias2 ? bias2[_o] : 0.f);                                \
            dst = Out + (long)n * oStride + (long)_o * HW + (pp);                      \
        }                                                                              \
        float2 r = {(v0) + bo_, (v1) + bo_};                                           \
        *reinterpret_cast<float2*>(dst) = r;                                           \
    } } while (0)

__global__ void __launch_bounds__(256)
mma_gemm_celu(const float* __restrict__ X, long xStride, int Cin,
              const float* __restrict__ W,
              const float* __restrict__ X2, long x2Stride, int Cin2,
              const float* __restrict__ W2,
              const float* __restrict__ bias, const float* __restrict__ bias2,
              int Cout, float* __restrict__ Out, long oStride,
              const float* __restrict__ WB, const float* __restrict__ biasB,
              float* __restrict__ OutB, long oStrideB, int Msplit) {
    __shared__ __align__(16) __half sA[2][64 * SAH];
    __shared__ __align__(16) __half sB[2][128 * SAH];
    const int tid  = threadIdx.x;
    const int warp = tid >> 5;
    const int lane = tid & 31;
    const int n  = blockIdx.y >> 3;
    const int p0 = (blockIdx.y & 7) * 128;
    const int o0 = blockIdx.x * 64;

    const int arow = tid >> 2;
    const int afs  = (tid & 3) * 8;
    const int bpx  = tid & 127;
    const int bf0  = (tid >> 7) * 16;
    const int m0w = (warp & 1) * 32;
    const int n0w = (warp >> 1) * 32;
    const int lq  = lane >> 2;
    const int lr  = lane & 3;

    const int nk1 = (2 * Cin + 31) >> 5;
    const int nk2 = W2 ? ((2 * Cin2 + 31) >> 5) : 0;
    const int nk  = nk1 + nk2;

    float areg[8], breg[16];
    float acc[2][4][4];
    #pragma unroll
    for (int mi = 0; mi < 2; ++mi)
        #pragma unroll
        for (int ni = 0; ni < 4; ++ni)
            #pragma unroll
            for (int e = 0; e < 4; ++e) acc[mi][ni][e] = 0.f;

    MG_LOAD_CHUNK(0);
    MG_STORE_CHUNK(0);
    __syncthreads();

    for (int k = 0; k < nk; ++k) {
        const int buf = k & 1;
        if (k + 1 < nk) MG_LOAD_CHUNK(k + 1);
        #pragma unroll
        for (int ks = 0; ks < 2; ++ks) {
            const int kb = ks * 16 + lr * 2;
            unsigned a[2][4], b[4][2];
            #pragma unroll
            for (int mi = 0; mi < 2; ++mi) {
                const __half* pa = &sA[buf][(m0w + mi * 16 + lq) * SAH + kb];
                a[mi][0] = *reinterpret_cast<const unsigned*>(pa);
                a[mi][1] = *reinterpret_cast<const unsigned*>(pa + 8 * SAH);
                a[mi][2] = *reinterpret_cast<const unsigned*>(pa + 8);
                a[mi][3] = *reinterpret_cast<const unsigned*>(pa + 8 * SAH + 8);
            }
            #pragma unroll
            for (int ni = 0; ni < 4; ++ni) {
                const __half* pb = &sB[buf][(n0w + ni * 8 + lq) * SAH + kb];
                b[ni][0] = *reinterpret_cast<const unsigned*>(pb);
                b[ni][1] = *reinterpret_cast<const unsigned*>(pb + 8);
            }
            #pragma unroll
            for (int mi = 0; mi < 2; ++mi)
                #pragma unroll
                for (int ni = 0; ni < 4; ++ni)
                    mma_f16(acc[mi][ni], a[mi], b[ni]);
        }
        if (k + 1 < nk) MG_STORE_CHUNK((k + 1) & 1);
        __syncthreads();
    }

    #pragma unroll
    for (int mi = 0; mi < 2; ++mi) {
        const int oa = o0 + m0w + mi * 16 + lq;
        #pragma unroll
        for (int ni = 0; ni < 4; ++ni) {
            const int pp = p0 + n0w + ni * 8 + 2 * lr;
            MG_EPI_WRITE(oa,     acc[mi][ni][0], acc[mi][ni][1], pp);
            MG_EPI_WRITE(oa + 8, acc[mi][ni][2], acc[mi][ni][3], pp);
        }
    }
}

// ---------------- gate: out = Xres + ga*sigmoid(gb), ga=G[c], gb=G[c+C] ----------------
__global__ void __launch_bounds__(256)
gate_kernel(const float* __restrict__ G, long gStride, int C,
            const float* __restrict__ Xres, long xStride,
            float* __restrict__ Out, long oStride, long total4) {
    long idx = (long)blockIdx.x * blockDim.x + threadIdx.x;
    if (idx >= total4) return;
    const int perImg = C * (HW / 4);
    const int n = (int)(idx / perImg);
    const int r = (int)(idx - (long)n * perImg);
    const int c = r / (HW / 4);
    const int p4 = (r - c * (HW / 4)) * 4;
    const float4 ga = *reinterpret_cast<const float4*>(&G[(long)n * gStride + (long)c * HW + p4]);
    const float4 gb = *reinterpret_cast<const float4*>(&G[(long)n * gStride + (long)(c + C) * HW + p4]);
    const float4 xr = *reinterpret_cast<const float4*>(&Xres[(long)n * xStride + (long)c * HW + p4]);
    float4 o;
    o.x = xr.x + ga.x / (1.f + expf(-gb.x));
    o.y = xr.y + ga.y / (1.f + expf(-gb.y));
    o.z = xr.z + ga.z / (1.f + expf(-gb.z));
    o.w = xr.w + ga.w / (1.f + expf(-gb.w));
    *reinterpret_cast<float4*>(&Out[(long)n * oStride + (long)c * HW + p4]) = o;
}

// ---------------- small projection body: Out[n, m0..m0+16, hw] = W*X + b ----------------
__device__ __forceinline__ void proj_body16(float* sW, const float* __restrict__ X, int Cin,
                                            const float* __restrict__ W,
                                            const float* __restrict__ bias,
                                            float* __restrict__ Out, int M, int m0) {
    const int n = blockIdx.y;
    const int p = blockIdx.x * 128 + threadIdx.x;
    for (int i = threadIdx.x; i < 16 * Cin; i += 128) {
        const int o = i / Cin, c = i - o * Cin;
        sW[o * 176 + c] = W[(long)(m0 + o) * Cin + c];
    }
    __syncthreads();
    const float* Xn = X + (long)n * Cin * HW;
    float acc[16];
    #pragma unroll
    for (int o = 0; o < 16; ++o) acc[o] = 0.f;
    #pragma unroll 4
    for (int c = 0; c < Cin; ++c) {
        const float v = Xn[(long)c * HW + p];
        #pragma unroll
        for (int o = 0; o < 16; ++o) acc[o] = fmaf(sW[o * 176 + c], v, acc[o]);
    }
    #pragma unroll
    for (int o = 0; o < 16; ++o)
        Out[((long)n * M + m0 + o) * HW + p] = acc[o] + bias[m0 + o];
}

__global__ void __launch_bounds__(128)
proj_kq_kernel(const float* __restrict__ XK, const float* __restrict__ XQ,
               const float* __restrict__ WK, const float* __restrict__ WQ,
               const float* __restrict__ bK, const float* __restrict__ bQ,
               float* __restrict__ OutK, float* __restrict__ OutQ) {
    __shared__ float sW[16 * 176];
    if (blockIdx.z == 0) proj_body16(sW, XK, CKC, WK, bK, OutK, KDIM, 0);
    else                 proj_body16(sW, XQ, CQC, WQ, bQ, OutQ, KDIM, 0);
}

__global__ void __launch_bounds__(128)
proj_v_kernel(const float* __restrict__ X, const float* __restrict__ W,
              const float* __restrict__ bias, float* __restrict__ Out) {
    __shared__ float sW[16 * 176];
    proj_body16(sW, X, CKC, W, bias, Out, VDIM, blockIdx.z * 16);
}

// ---------------- presoftmax: S[n,q,k] = sum_j K[n,j,k]*Q[n,j,q]  (lower tiles only) ----------------
__global__ void qk_kernel(const float* __restrict__ Kt, const float* __restrict__ Qt,
                          float* __restrict__ S) {
    const int n  = blockIdx.z;
    const int q0 = blockIdx.y * 64;
    const int k0 = blockIdx.x * 64;
    if (k0 > q0) return;
    __shared__ float sK[16][64];
    __shared__ float sQ[16][64];
    const float* Kn = Kt + (long)n * KDIM * HW;
    const float* Qn = Qt + (long)n * KDIM * HW;
    const int p  = threadIdx.x & 63;
    const int jr = threadIdx.x >> 6;
    #pragma unroll
    for (int pass = 0; pass < 4; ++pass) {
        const int j = jr + pass * 4;
        sK[j][p] = Kn[(long)j * HW + k0 + p];
        sQ[j][p] = Qn[(long)j * HW + q0 + p];
    }
    __syncthreads();
    const int tx = threadIdx.x & 15, ty = threadIdx.x >> 4;
    float acc[4][4] = {};
    #pragma unroll
    for (int j = 0; j < 16; ++j) {
        const float4 q4 = *reinterpret_cast<const float4*>(&sQ[j][ty * 4]);
        const float4 k4 = *reinterpret_cast<const float4*>(&sK[j][tx * 4]);
        const float qr[4] = {q4.x, q4.y, q4.z, q4.w};
        const float kr[4] = {k4.x, k4.y, k4.z, k4.w};
        #pragma unroll
        for (int i = 0; i < 4; ++i)
            #pragma unroll
            for (int jj = 0; jj < 4; ++jj)
                acc[i][jj] = fmaf(qr[i], kr[jj], acc[i][jj]);
    }
    float* Sn = S + (long)n * HW * HW;
    #pragma unroll
    for (int i = 0; i < 4; ++i) {
        float4 r = {acc[i][0], acc[i][1], acc[i][2], acc[i][3]};
        *reinterpret_cast<float4*>(&Sn[(long)(q0 + ty * 4 + i) * HW + k0 + tx * 4]) = r;
    }
}

// ---------------- causal softmax per row (faithful semantics) ----------------
__global__ void softmax_kernel(float* __restrict__ S) {
    const int q = blockIdx.x;
    const int n = blockIdx.y;
    float* row = S + ((long)n * HW + (long)q) * HW;
    const int tid = threadIdx.x;  // 256
    __shared__ float red[256];

    float vals[4];
    float lmax = 0.f;
    #pragma unroll
    for (int i = 0; i < 4; ++i) {
        const int k = tid + i * 256;
        const float s = (k < q) ? row[k] : 0.f;
        vals[i] = s;
        if (k < q) lmax = fmaxf(lmax, s);
    }
    red[tid] = lmax;
    __syncthreads();
    for (int s2 = 128; s2 > 0; s2 >>= 1) {
        if (tid < s2) red[tid] = fmaxf(red[tid], red[tid + s2]);
        __syncthreads();
    }
    const float m = red[0];
    __syncthreads();

    float e[4];
    float lsum = 0.f;
    #pragma unroll
    for (int i = 0; i < 4; ++i) {
        const int k = tid + i * 256;
        e[i] = (k < q) ? expf(vals[i] - m) : 0.f;
        lsum += e[i];
    }
    red[tid] = lsum;
    __syncthreads();
    for (int s2 = 128; s2 > 0; s2 >>= 1) {
        if (tid < s2) red[tid] += red[tid + s2];
        __syncthreads();
    }
    const float Skept = red[0];
    const float D = Skept + (float)(HW - q) * expf(-m);
    const float inv = 1.f / (Skept + 1e-7f * D);
    const int kmax = (q & ~63) + 64;   // av only consumes k < roundup(q+1, 64)
    #pragma unroll
    for (int i = 0; i < 4; ++i) {
        const int k = tid + i * 256;
        if (k < kmax) row[k] = e[i] * inv;
    }
}

// ---------------- AV: Out[n,v,q] = sum_j Att[n,q,j] * V[n,v,j]  (K causally truncated) ----------------
__global__ void av_kernel(const float* __restrict__ Att, const float* __restrict__ V,
                          float* __restrict__ Out) {
    __shared__ float sV[16][80];
    __shared__ float sW[16][64];
    const int n  = blockIdx.y;
    const int q0 = blockIdx.x * 64;
    const float* An = Att + (long)n * HW * HW;
    const float* Vn = V + (long)n * VDIM * HW;
    const int tx = threadIdx.x & 15, ty = threadIdx.x >> 4;
    float acc[5][4] = {};
    const int jmax = min(HW, q0 + 64);

    for (int j0 = 0; j0 < jmax; j0 += 16) {
        for (int i = threadIdx.x; i < 16 * 80; i += 256) {
            const int v = i >> 4, jj = i & 15;
            sV[jj][v] = Vn[(long)v * HW + j0 + jj];
        }
        for (int i = threadIdx.x; i < 16 * 64; i += 256) {
            const int qq = i >> 4, jj = i & 15;
            sW[jj][qq] = An[(long)(q0 + qq) * HW + j0 + jj];
        }
        __syncthreads();
        #pragma unroll
        for (int jj = 0; jj < 16; ++jj) {
            const float4 w4 = *reinterpret_cast<const float4*>(&sW[jj][tx * 4]);
            const float wv[4] = {w4.x, w4.y, w4.z, w4.w};
            #pragma unroll
            for (int i = 0; i < 5; ++i) {
                const float vv = sV[jj][ty * 5 + i];
                #pragma unroll
                for (int j = 0; j < 4; ++j)
                    acc[i][j] = fmaf(vv, wv[j], acc[i][j]);
            }
        }
        __syncthreads();
    }
    #pragma unroll
    for (int i = 0; i < 5; ++i) {
        float4 r = {acc[i][0], acc[i][1], acc[i][2], acc[i][3]};
        *reinterpret_cast<float4*>(&Out[((long)n * VDIM + ty * 5 + i) * HW + q0 + tx * 4]) = r;
    }
}

// ---------------- launcher ----------------
extern "C" void kernel_launch(void* const* d_in, const int* in_sizes, int n_in,
                              void* d_out, int out_size) {
    (void)in_sizes; (void)n_in; (void)out_size;
    const float* x    = (const float*)d_in[0];
    const float* ul   = (const float*)d_in[1];
    const float* b    = (const float*)d_in[2];
    const float* gkWi = (const float*)d_in[3];
    const float* gkbi = (const float*)d_in[4];
    const float* gkWo = (const float*)d_in[5];
    const float* gkbo = (const float*)d_in[6];
    const float* gqWi = (const float*)d_in[7];
    const float* gqbi = (const float*)d_in[8];
    const float* gqWo = (const float*)d_in[9];
    const float* gqbo = (const float*)d_in[10];
    const float* gvWi = (const float*)d_in[11];
    const float* gvbi = (const float*)d_in[12];
    const float* gvWo = (const float*)d_in[13];
    const float* gvbo = (const float*)d_in[14];
    const float* nkW  = (const float*)d_in[15];
    const float* nkb  = (const float*)d_in[16];
    const float* nqW  = (const float*)d_in[17];
    const float* nqb  = (const float*)d_in[18];
    const float* nvW  = (const float*)d_in[19];
    const float* nvb  = (const float*)d_in[20];
    const float* goWi = (const float*)d_in[21];
    const float* gobi = (const float*)d_in[22];
    const float* goWs = (const float*)d_in[23];
    const float* gobs = (const float*)d_in[24];
    const float* goWo = (const float*)d_in[25];
    const float* gobo = (const float*)d_in[26];
    float* out = (float*)d_out;

    float *p_cat, *p_h, *p_h2, *p_big, *p_gout, *p_gout2, *p_keys, *p_quer, *p_vals, *p_att, *p_attv;
    cudaGetSymbolAddress((void**)&p_cat,   g_cat);
    cudaGetSymbolAddress((void**)&p_h,     g_h);
    cudaGetSymbolAddress((void**)&p_h2,    g_h2);
    cudaGetSymbolAddress((void**)&p_big,   g_big);
    cudaGetSymbolAddress((void**)&p_gout,  g_gout);
    cudaGetSymbolAddress((void**)&p_gout2, g_gout2);
    cudaGetSymbolAddress((void**)&p_keys,  g_keys);
    cudaGetSymbolAddress((void**)&p_quer,  g_quer);
    cudaGetSymbolAddress((void**)&p_vals,  g_vals);
    cudaGetSymbolAddress((void**)&p_att,   g_att);
    cudaGetSymbolAddress((void**)&p_attv,  g_attv);

    const long sCat = (long)CKC * HW;
    const long sQ   = (long)CQC * HW;
    const long sO   = (long)COC * HW;
    const long sV   = (long)VDIM * HW;
    const long sBig = (long)2 * CKC * HW;

    {
        const long total = (long)NB * CKC * HW;
        build_cat_kernel<<<(unsigned)((total + 255) / 256), 256>>>(x, ul, b, p_cat);
    }

    const dim3 gridKV (6, NB * 8);   // K+V fused stage-1: 338 rows
    const dim3 gridS1 (3, NB * 8);   // Cout<=169
    const dim3 gridS2K(6, NB * 8);   // 338
    const dim3 gridS2Q(6, NB * 8);   // 332
    const dim3 gridS2O(5, NB * 8);   // 320

    // ---- Stage-1 K+V fused (shared input & celu B tile) ----
    mma_gemm_celu<<<gridKV, 256>>>(p_cat, sCat, CKC, gkWi, nullptr, 0, 0, nullptr,
                                   gkbi, nullptr, 2 * CKC, p_h, sCat,
                                   gvWi, gvbi, p_h2, sCat, CKC);

    // ---- K chain: stage-2 -> gate -> gout ----
    mma_gemm_celu<<<gridS2K, 256>>>(p_h, sCat, CKC, gkWo, nullptr, 0, 0, nullptr,
                                    gkbo, nullptr, 2 * CKC, p_big, sBig,
                                    nullptr, nullptr, nullptr, 0, 1 << 30);
    {
        const long t4 = (long)NB * CKC * (HW / 4);
        gate_kernel<<<(unsigned)((t4 + 255) / 256), 256>>>(p_big, sBig, CKC, p_cat, sCat, p_gout, sCat, t4);
    }

    // ---- V chain: stage-2 -> gate -> gout2 ----
    mma_gemm_celu<<<gridS2K, 256>>>(p_h2, sCat, CKC, gvWo, nullptr, 0, 0, nullptr,
                                    gvbo, nullptr, 2 * CKC, p_big, sBig,
                                    nullptr, nullptr, nullptr, 0, 1 << 30);
    {
        const long t4 = (long)NB * CKC * (HW / 4);
        gate_kernel<<<(unsigned)((t4 + 255) / 256), 256>>>(p_big, sBig, CKC, p_cat, sCat, p_gout2, sCat, t4);
    }

    // ---- Q chain (ul_b view): stage-1 -> stage-2 -> gate -> h2 (reused) ----
    mma_gemm_celu<<<gridS1, 256>>>(p_cat + 3 * HW, sCat, CQC, gqWi, nullptr, 0, 0, nullptr,
                                   gqbi, nullptr, CQC, p_h, sQ,
                                   nullptr, nullptr, nullptr, 0, 1 << 30);
    mma_gemm_celu<<<gridS2Q, 256>>>(p_h, sQ, CQC, gqWo, nullptr, 0, 0, nullptr,
                                    gqbo, nullptr, 2 * CQC, p_big, sBig,
                                    nullptr, nullptr, nullptr, 0, 1 << 30);
    {
        const long t4 = (long)NB * CQC * (HW / 4);
        gate_kernel<<<(unsigned)((t4 + 255) / 256), 256>>>(p_big, sBig, CQC, p_cat + 3 * HW, sCat, p_h2, sQ, t4);
    }

    // ---- projections ----
    proj_kq_kernel<<<dim3(8, NB, 2), 128>>>(p_gout, p_h2, nkW, nqW, nkb, nqb, p_keys, p_quer);
    proj_v_kernel <<<dim3(8, NB, 5), 128>>>(p_gout2, nvW, nvb, p_vals);

    // ---- attention ----
    qk_kernel<<<dim3(16, 16, NB), 256>>>(p_keys, p_quer, p_att);
    softmax_kernel<<<dim3(HW, NB), 256>>>(p_att);
    av_kernel<<<dim3(16, NB), 256>>>(p_att, p_vals, p_attv);

    // ---- O chain: dual-input stage-1 -> stage-2 -> gate -> output ----
    mma_gemm_celu<<<gridS1, 256>>>(ul, sO, COC, goWi, p_attv, sV, VDIM, goWs,
                                   gobi, gobs, COC, p_h, sO,
                                   nullptr, nullptr, nullptr, 0, 1 << 30);
    mma_gemm_celu<<<gridS2O, 256>>>(p_h, sO, COC, goWo, nullptr, 0, 0, nullptr,
                                    gobo, nullptr, 2 * COC, p_big, sBig,
                                    nullptr, nullptr, nullptr, 0, 1 << 30);
    {
        const long t4 = (long)NB * COC * (HW / 4);
        gate_kernel<<<(unsigned)((t4 + 255) / 256), 256>>>(p_big, sBig, COC, ul, sO, out, sO, t4);
    }
}

// round 11
// speedup vs baseline: 1.3376x; 1.3376x over previous
#include <cuda_runtime.h>
#include <cuda_fp16.h>
#include <math.h>
#include <stdint.h>

#define NB 32
#define HW 1024

#define CKC 169   // x_ul_b channels
#define CQC 166   // ul_b channels
#define COC 160   // ul channels
#define KDIM 16
#define VDIM 80

// ---------------- scratch (static device memory; no allocations) ----------------
__device__ float g_cat [(size_t)NB * CKC * HW];       // x_ul_b [n,169,1024]; ul_b = view +3*HW
__device__ float g_h   [(size_t)NB * CKC * HW];       // GRN hidden
__device__ float g_big [(size_t)NB * 2 * CKC * HW];   // GRN stage-2 raw [2C, hw]
__device__ float g_gout[(size_t)NB * CKC * HW];       // GRN output
__device__ float g_keys[(size_t)NB * KDIM * HW];
__device__ float g_quer[(size_t)NB * KDIM * HW];
__device__ float g_vals[(size_t)NB * VDIM * HW];
__device__ float g_att [(size_t)NB * HW * HW];
__device__ float g_attv[(size_t)NB * VDIM * HW];

__device__ __forceinline__ float eluf(float v) { return v > 0.f ? v : (expf(v) - 1.f); }

__device__ __forceinline__ void mma_f16(float* d, const unsigned* a, const unsigned* b) {
    asm volatile(
        "mma.sync.aligned.m16n8k16.row.col.f32.f16.f16.f32 "
        "{%0,%1,%2,%3}, {%4,%5,%6,%7}, {%8,%9}, {%0,%1,%2,%3};"
        : "+f"(d[0]), "+f"(d[1]), "+f"(d[2]), "+f"(d[3])
        : "r"(a[0]), "r"(a[1]), "r"(a[2]), "r"(a[3]), "r"(b[0]), "r"(b[1]));
}

// ---------------- concat inputs into [n,169,hw] ----------------
__global__ void build_cat_kernel(const float* __restrict__ x, const float* __restrict__ ul,
                                 const float* __restrict__ b, float* __restrict__ cat) {
    long idx = (long)blockIdx.x * blockDim.x + threadIdx.x;
    const long total = (long)NB * CKC * HW;
    if (idx >= total) return;
    int p = (int)(idx % HW);
    int c = (int)((idx / HW) % CKC);
    int n = (int)(idx / ((long)CKC * HW));
    float v;
    if (c < 3)        v = x [((long)n * 3   + c        ) * HW + p];
    else if (c < 163) v = ul[((long)n * 160 + (c - 3)  ) * HW + p];
    else              v = b [((long)n * 6   + (c - 163)) * HW + p];
    cat[idx] = v;
}

// ============ FP16 MMA GEMM (R8-proven): Out = W*concat_elu(X) [+ W2*concat_elu(X2)] + bias[+bias2]
// CTA tile: 64 out x 128 px, 256 threads = 8 warps (2 M-groups x 4 N-groups), warp tile 32x32.
// K chunks of 32 features, TWO smem buffer pairs, ONE sync per chunk (ping-pong).

#define SAH 34   // smem stride in halves

#define MG_LOAD_CHUNK(kk)                                                              \
    {                                                                                  \
        const float* Xs; const float* Ws; int Ci; long xs; int fb;                     \
        if ((kk) < nk1) { Xs = X;  Ws = W;  Ci = Cin;  xs = xStride;  fb = (kk) * 32; } \
        else            { Xs = X2; Ws = W2; Ci = Cin2; xs = x2Stride; fb = ((kk) - nk1) * 32; } \
        const int lim = 2 * Ci;                                                        \
        const int o = o0 + arow;                                                       \
        const bool oOK = o < Cout;                                                     \
        _Pragma("unroll")                                                              \
        for (int jj = 0; jj < 4; ++jj) {                                               \
            const int f = fb + afs + 2 * jj;                                           \
            float2 w2 = {0.f, 0.f};                                                    \
            if (oOK && f < lim)                                                        \
                w2 = *reinterpret_cast<const float2*>(&Ws[(long)o * lim + f]);         \
            areg[2 * jj] = w2.x; areg[2 * jj + 1] = w2.y;                              \
        }                                                                              \
        const float* Xn = Xs + (long)n * xs;                                           \
        _Pragma("unroll")                                                              \
        for (int j = 0; j < 16; ++j) {                                                 \
            const int ff = fb + bf0 + j;                                               \
            float v = 0.f;                                                             \
            if (ff < lim) {                                                            \
                const int c  = (ff < Ci) ? ff : (ff - Ci);                             \
                const float xv = Xn[(long)c * HW + p0 + bpx];                          \
                v = (ff < Ci) ? eluf(xv) : eluf(-xv);                                  \
            }                                                                          \
            breg[j] = v;                                                               \
        }                                                                              \
    }

#define MG_STORE_CHUNK(buf)                                                            \
    {                                                                                  \
        __half* pa = &sA[buf][arow * SAH + afs];                                       \
        _Pragma("unroll")                                                              \
        for (int jj = 0; jj < 4; ++jj)                                                 \
            *reinterpret_cast<__half2*>(pa + 2 * jj) =                                 \
                __floats2half2_rn(areg[2 * jj], areg[2 * jj + 1]);                     \
        __half* pb = &sB[buf][bpx * SAH + bf0];                                        \
        _Pragma("unroll")                                                              \
        for (int jj = 0; jj < 8; ++jj)                                                 \
            *reinterpret_cast<__half2*>(pb + 2 * jj) =                                 \
                __floats2half2_rn(breg[2 * jj], breg[2 * jj + 1]);                     \
    }

__global__ void __launch_bounds__(256)
mma_gemm_celu(const float* __restrict__ X, long xStride, int Cin,
              const float* __restrict__ W,
              const float* __restrict__ X2, long x2Stride, int Cin2,
              const float* __restrict__ W2,
              const float* __restrict__ bias, const float* __restrict__ bias2,
              int Cout, float* __restrict__ Out, long oStride) {
    __shared__ __align__(16) __half sA[2][64 * SAH];
    __shared__ __align__(16) __half sB[2][128 * SAH];
    const int tid  = threadIdx.x;
    const int warp = tid >> 5;
    const int lane = tid & 31;
    const int n  = blockIdx.y >> 3;
    const int p0 = (blockIdx.y & 7) * 128;
    const int o0 = blockIdx.x * 64;

    const int arow = tid >> 2;          // A: out row (0..63)
    const int afs  = (tid & 3) * 8;     // A: feature offset
    const int bpx  = tid & 127;         // B: pixel
    const int bf0  = (tid >> 7) * 16;   // B: feature group
    const int m0w = (warp & 1) * 32;
    const int n0w = (warp >> 1) * 32;
    const int lq  = lane >> 2;
    const int lr  = lane & 3;

    const int nk1 = (2 * Cin + 31) >> 5;
    const int nk2 = W2 ? ((2 * Cin2 + 31) >> 5) : 0;
    const int nk  = nk1 + nk2;

    float areg[8], breg[16];
    float acc[2][4][4];
    #pragma unroll
    for (int mi = 0; mi < 2; ++mi)
        #pragma unroll
        for (int ni = 0; ni < 4; ++ni)
            #pragma unroll
            for (int e = 0; e < 4; ++e) acc[mi][ni][e] = 0.f;

    MG_LOAD_CHUNK(0);
    MG_STORE_CHUNK(0);
    __syncthreads();

    for (int k = 0; k < nk; ++k) {
        const int buf = k & 1;
        if (k + 1 < nk) MG_LOAD_CHUNK(k + 1);
        #pragma unroll
        for (int ks = 0; ks < 2; ++ks) {
            const int kb = ks * 16 + lr * 2;
            unsigned a[2][4], b[4][2];
            #pragma unroll
            for (int mi = 0; mi < 2; ++mi) {
                const __half* pa = &sA[buf][(m0w + mi * 16 + lq) * SAH + kb];
                a[mi][0] = *reinterpret_cast<const unsigned*>(pa);
                a[mi][1] = *reinterpret_cast<const unsigned*>(pa + 8 * SAH);
                a[mi][2] = *reinterpret_cast<const unsigned*>(pa + 8);
                a[mi][3] = *reinterpret_cast<const unsigned*>(pa + 8 * SAH + 8);
            }
            #pragma unroll
            for (int ni = 0; ni < 4; ++ni) {
                const __half* pb = &sB[buf][(n0w + ni * 8 + lq) * SAH + kb];
                b[ni][0] = *reinterpret_cast<const unsigned*>(pb);
                b[ni][1] = *reinterpret_cast<const unsigned*>(pb + 8);
            }
            #pragma unroll
            for (int mi = 0; mi < 2; ++mi)
                #pragma unroll
                for (int ni = 0; ni < 4; ++ni)
                    mma_f16(acc[mi][ni], a[mi], b[ni]);
        }
        if (k + 1 < nk) MG_STORE_CHUNK((k + 1) & 1);
        __syncthreads();
    }

    #pragma unroll
    for (int mi = 0; mi < 2; ++mi) {
        const int oa = o0 + m0w + mi * 16 + lq;
        const int ob = oa + 8;
        const float ba = (oa < Cout) ? (bias[oa] + (bias2 ? bias2[oa] : 0.f)) : 0.f;
        const float bb = (ob < Cout) ? (bias[ob] + (bias2 ? bias2[ob] : 0.f)) : 0.f;
        #pragma unroll
        for (int ni = 0; ni < 4; ++ni) {
            const int pp = p0 + n0w + ni * 8 + 2 * lr;
            if (oa < Cout) {
                float2 r = {acc[mi][ni][0] + ba, acc[mi][ni][1] + ba};
                *reinterpret_cast<float2*>(&Out[(long)n * oStride + (long)oa * HW + pp]) = r;
            }
            if (ob < Cout) {
                float2 r = {acc[mi][ni][2] + bb, acc[mi][ni][3] + bb};
                *reinterpret_cast<float2*>(&Out[(long)n * oStride + (long)ob * HW + pp]) = r;
            }
        }
    }
}

// ---------------- gate: out = Xres + ga*sigmoid(gb), ga=G[c], gb=G[c+C] ----------------
__global__ void __launch_bounds__(256)
gate_kernel(const float* __restrict__ G, long gStride, int C,
            const float* __restrict__ Xres, long xStride,
            float* __restrict__ Out, long oStride, long total4) {
    long idx = (long)blockIdx.x * blockDim.x + threadIdx.x;
    if (idx >= total4) return;
    const int perImg = C * (HW / 4);
    const int n = (int)(idx / perImg);
    const int r = (int)(idx - (long)n * perImg);
    const int c = r / (HW / 4);
    const int p4 = (r - c * (HW / 4)) * 4;
    const float4 ga = *reinterpret_cast<const float4*>(&G[(long)n * gStride + (long)c * HW + p4]);
    const float4 gb = *reinterpret_cast<const float4*>(&G[(long)n * gStride + (long)(c + C) * HW + p4]);
    const float4 xr = *reinterpret_cast<const float4*>(&Xres[(long)n * xStride + (long)c * HW + p4]);
    float4 o;
    o.x = xr.x + ga.x / (1.f + expf(-gb.x));
    o.y = xr.y + ga.y / (1.f + expf(-gb.y));
    o.z = xr.z + ga.z / (1.f + expf(-gb.z));
    o.w = xr.w + ga.w / (1.f + expf(-gb.w));
    *reinterpret_cast<float4*>(&Out[(long)n * oStride + (long)c * HW + p4]) = o;
}

// ---------------- small projection: Out[n, m0..m0+16, hw] = W*X + b ----------------
// 128 threads, grid (8, NB, M/16) -> 256..1280 CTAs (occupancy fix; kernel body unchanged math)
__global__ void __launch_bounds__(128)
proj16_kernel(const float* __restrict__ X, int Cin,
              const float* __restrict__ W, const float* __restrict__ bias,
              float* __restrict__ Out, int M) {
    __shared__ float sW[16 * 176];
    const int n  = blockIdx.y;
    const int m0 = blockIdx.z * 16;
    const int p  = blockIdx.x * 128 + threadIdx.x;
    for (int i = threadIdx.x; i < 16 * Cin; i += 128) {
        const int o = i / Cin, c = i - o * Cin;
        sW[o * 176 + c] = W[(long)(m0 + o) * Cin + c];
    }
    __syncthreads();
    const float* Xn = X + (long)n * Cin * HW;
    float acc[16];
    #pragma unroll
    for (int o = 0; o < 16; ++o) acc[o] = 0.f;
    #pragma unroll 4
    for (int c = 0; c < Cin; ++c) {
        const float v = Xn[(long)c * HW + p];
        #pragma unroll
        for (int o = 0; o < 16; ++o) acc[o] = fmaf(sW[o * 176 + c], v, acc[o]);
    }
    #pragma unroll
    for (int o = 0; o < 16; ++o)
        Out[((long)n * M + m0 + o) * HW + p] = acc[o] + bias[m0 + o];
}

// ---------------- presoftmax: S[n,q,k] = sum_j K[n,j,k]*Q[n,j,q]  (lower tiles only) ----------------
__global__ void qk_kernel(const float* __restrict__ Kt, const float* __restrict__ Qt,
                          float* __restrict__ S) {
    const int n  = blockIdx.z;
    const int q0 = blockIdx.y * 64;
    const int k0 = blockIdx.x * 64;
    if (k0 > q0) return;
    __shared__ float sK[16][64];
    __shared__ float sQ[16][64];
    const float* Kn = Kt + (long)n * KDIM * HW;
    const float* Qn = Qt + (long)n * KDIM * HW;
    const int p  = threadIdx.x & 63;
    const int jr = threadIdx.x >> 6;
    #pragma unroll
    for (int pass = 0; pass < 4; ++pass) {
        const int j = jr + pass * 4;
        sK[j][p] = Kn[(long)j * HW + k0 + p];
        sQ[j][p] = Qn[(long)j * HW + q0 + p];
    }
    __syncthreads();
    const int tx = threadIdx.x & 15, ty = threadIdx.x >> 4;
    float acc[4][4] = {};
    #pragma unroll
    for (int j = 0; j < 16; ++j) {
        const float4 q4 = *reinterpret_cast<const float4*>(&sQ[j][ty * 4]);
        const float4 k4 = *reinterpret_cast<const float4*>(&sK[j][tx * 4]);
        const float qr[4] = {q4.x, q4.y, q4.z, q4.w};
        const float kr[4] = {k4.x, k4.y, k4.z, k4.w};
        #pragma unroll
        for (int i = 0; i < 4; ++i)
            #pragma unroll
            for (int jj = 0; jj < 4; ++jj)
                acc[i][jj] = fmaf(qr[i], kr[jj], acc[i][jj]);
    }
    float* Sn = S + (long)n * HW * HW;
    #pragma unroll
    for (int i = 0; i < 4; ++i) {
        float4 r = {acc[i][0], acc[i][1], acc[i][2], acc[i][3]};
        *reinterpret_cast<float4*>(&Sn[(long)(q0 + ty * 4 + i) * HW + k0 + tx * 4]) = r;
    }
}

// ---------------- causal softmax per row (faithful semantics) ----------------
__global__ void softmax_kernel(float* __restrict__ S) {
    const int q = blockIdx.x;
    const int n = blockIdx.y;
    float* row = S + ((long)n * HW + (long)q) * HW;
    const int tid = threadIdx.x;  // 256
    __shared__ float red[256];

    float vals[4];
    float lmax = 0.f;
    #pragma unroll
    for (int i = 0; i < 4; ++i) {
        const int k = tid + i * 256;
        const float s = (k < q) ? row[k] : 0.f;
        vals[i] = s;
        if (k < q) lmax = fmaxf(lmax, s);
    }
    red[tid] = lmax;
    __syncthreads();
    for (int s2 = 128; s2 > 0; s2 >>= 1) {
        if (tid < s2) red[tid] = fmaxf(red[tid], red[tid + s2]);
        __syncthreads();
    }
    const float m = red[0];
    __syncthreads();

    float e[4];
    float lsum = 0.f;
    #pragma unroll
    for (int i = 0; i < 4; ++i) {
        const int k = tid + i * 256;
        e[i] = (k < q) ? expf(vals[i] - m) : 0.f;
        lsum += e[i];
    }
    red[tid] = lsum;
    __syncthreads();
    for (int s2 = 128; s2 > 0; s2 >>= 1) {
        if (tid < s2) red[tid] += red[tid + s2];
        __syncthreads();
    }
    const float Skept = red[0];
    const float D = Skept + (float)(HW - q) * expf(-m);
    const float inv = 1.f / (Skept + 1e-7f * D);
    const int kmax = (q & ~63) + 64;   // av only consumes k < roundup(q+1, 64)
    #pragma unroll
    for (int i = 0; i < 4; ++i) {
        const int k = tid + i * 256;
        if (k < kmax) row[k] = e[i] * inv;
    }
}

// ---------------- AV: Out[n,v,q] = sum_j Att[n,q,j] * V[n,v,j]  (K causally truncated) ----------------
__global__ void av_kernel(const float* __restrict__ Att, const float* __restrict__ V,
                          float* __restrict__ Out) {
    __shared__ float sV[16][80];
    __shared__ float sW[16][64];
    const int n  = blockIdx.y;
    const int q0 = blockIdx.x * 64;
    const float* An = Att + (long)n * HW * HW;
    const float* Vn = V + (long)n * VDIM * HW;
    const int tx = threadIdx.x & 15, ty = threadIdx.x >> 4;
    float acc[5][4] = {};
    const int jmax = min(HW, q0 + 64);

    for (int j0 = 0; j0 < jmax; j0 += 16) {
        for (int i = threadIdx.x; i < 16 * 80; i += 256) {
            const int v = i >> 4, jj = i & 15;
            sV[jj][v] = Vn[(long)v * HW + j0 + jj];
        }
        for (int i = threadIdx.x; i < 16 * 64; i += 256) {
            const int qq = i >> 4, jj = i & 15;
            sW[jj][qq] = An[(long)(q0 + qq) * HW + j0 + jj];
        }
        __syncthreads();
        #pragma unroll
        for (int jj = 0; jj < 16; ++jj) {
            const float4 w4 = *reinterpret_cast<const float4*>(&sW[jj][tx * 4]);
            const float wv[4] = {w4.x, w4.y, w4.z, w4.w};
            #pragma unroll
            for (int i = 0; i < 5; ++i) {
                const float vv = sV[jj][ty * 5 + i];
                #pragma unroll
                for (int j = 0; j < 4; ++j)
                    acc[i][j] = fmaf(vv, wv[j], acc[i][j]);
            }
        }
        __syncthreads();
    }
    #pragma unroll
    for (int i = 0; i < 5; ++i) {
        float4 r = {acc[i][0], acc[i][1], acc[i][2], acc[i][3]};
        *reinterpret_cast<float4*>(&Out[((long)n * VDIM + ty * 5 + i) * HW + q0 + tx * 4]) = r;
    }
}

// ---------------- launcher ----------------
extern "C" void kernel_launch(void* const* d_in, const int* in_sizes, int n_in,
                              void* d_out, int out_size) {
    (void)in_sizes; (void)n_in; (void)out_size;
    const float* x    = (const float*)d_in[0];
    const float* ul   = (const float*)d_in[1];
    const float* b    = (const float*)d_in[2];
    const float* gkWi = (const float*)d_in[3];
    const float* gkbi = (const float*)d_in[4];
    const float* gkWo = (const float*)d_in[5];
    const float* gkbo = (const float*)d_in[6];
    const float* gqWi = (const float*)d_in[7];
    const float* gqbi = (const float*)d_in[8];
    const float* gqWo = (const float*)d_in[9];
    const float* gqbo = (const float*)d_in[10];
    const float* gvWi = (const float*)d_in[11];
    const float* gvbi = (const float*)d_in[12];
    const float* gvWo = (const float*)d_in[13];
    const float* gvbo = (const float*)d_in[14];
    const float* nkW  = (const float*)d_in[15];
    const float* nkb  = (const float*)d_in[16];
    const float* nqW  = (const float*)d_in[17];
    const float* nqb  = (const float*)d_in[18];
    const float* nvW  = (const float*)d_in[19];
    const float* nvb  = (const float*)d_in[20];
    const float* goWi = (const float*)d_in[21];
    const float* gobi = (const float*)d_in[22];
    const float* goWs = (const float*)d_in[23];
    const float* gobs = (const float*)d_in[24];
    const float* goWo = (const float*)d_in[25];
    const float* gobo = (const float*)d_in[26];
    float* out = (float*)d_out;

    float *p_cat, *p_h, *p_big, *p_gout, *p_keys, *p_quer, *p_vals, *p_att, *p_attv;
    cudaGetSymbolAddress((void**)&p_cat,  g_cat);
    cudaGetSymbolAddress((void**)&p_h,    g_h);
    cudaGetSymbolAddress((void**)&p_big,  g_big);
    cudaGetSymbolAddress((void**)&p_gout, g_gout);
    cudaGetSymbolAddress((void**)&p_keys, g_keys);
    cudaGetSymbolAddress((void**)&p_quer, g_quer);
    cudaGetSymbolAddress((void**)&p_vals, g_vals);
    cudaGetSymbolAddress((void**)&p_att,  g_att);
    cudaGetSymbolAddress((void**)&p_attv, g_attv);

    const long sCat = (long)CKC * HW;
    const long sQ   = (long)CQC * HW;
    const long sO   = (long)COC * HW;
    const long sV   = (long)VDIM * HW;
    const long sBig = (long)2 * CKC * HW;

    {
        const long total = (long)NB * CKC * HW;
        build_cat_kernel<<<(unsigned)((total + 255) / 256), 256>>>(x, ul, b, p_cat);
    }

    const dim3 gridS1(3, NB * 8);    // Cout<=169 -> 3 out-tiles of 64
    const dim3 gridS2K(6, NB * 8);   // Cout=338 -> 6
    const dim3 gridS2Q(6, NB * 8);   // Cout=332 -> 6
    const dim3 gridS2O(5, NB * 8);   // Cout=320 -> 5

    // ---- GRN-K -> keys ----
    mma_gemm_celu<<<gridS1, 256>>>(p_cat, sCat, CKC, gkWi, nullptr, 0, 0, nullptr,
                                   gkbi, nullptr, CKC, p_h, sCat);
    mma_gemm_celu<<<gridS2K, 256>>>(p_h, sCat, CKC, gkWo, nullptr, 0, 0, nullptr,
                                    gkbo, nullptr, 2 * CKC, p_big, sBig);
    {
        const long t4 = (long)NB * CKC * (HW / 4);
        gate_kernel<<<(unsigned)((t4 + 255) / 256), 256>>>(p_big, sBig, CKC, p_cat, sCat, p_gout, sCat, t4);
    }
    proj16_kernel<<<dim3(8, NB, 1), 128>>>(p_gout, CKC, nkW, nkb, p_keys, KDIM);

    // ---- GRN-Q -> queries (ul_b is a channel-offset view of cat) ----
    mma_gemm_celu<<<gridS1, 256>>>(p_cat + 3 * HW, sCat, CQC, gqWi, nullptr, 0, 0, nullptr,
                                   gqbi, nullptr, CQC, p_h, sQ);
    mma_gemm_celu<<<gridS2Q, 256>>>(p_h, sQ, CQC, gqWo, nullptr, 0, 0, nullptr,
                                    gqbo, nullptr, 2 * CQC, p_big, sBig);
    {
        const long t4 = (long)NB * CQC * (HW / 4);
        gate_kernel<<<(unsigned)((t4 + 255) / 256), 256>>>(p_big, sBig, CQC, p_cat + 3 * HW, sCat, p_gout, sQ, t4);
    }
    proj16_kernel<<<dim3(8, NB, 1), 128>>>(p_gout, CQC, nqW, nqb, p_quer, KDIM);

    // ---- GRN-V -> values ----
    mma_gemm_celu<<<gridS1, 256>>>(p_cat, sCat, CKC, gvWi, nullptr, 0, 0, nullptr,
                                   gvbi, nullptr, CKC, p_h, sCat);
    mma_gemm_celu<<<gridS2K, 256>>>(p_h, sCat, CKC, gvWo, nullptr, 0, 0, nullptr,
                                    gvbo, nullptr, 2 * CKC, p_big, sBig);
    {
        const long t4 = (long)NB * CKC * (HW / 4);
        gate_kernel<<<(unsigned)((t4 + 255) / 256), 256>>>(p_big, sBig, CKC, p_cat, sCat, p_gout, sCat, t4);
    }
    proj16_kernel<<<dim3(8, NB, 5), 128>>>(p_gout, CKC, nvW, nvb, p_vals, VDIM);

    // ---- attention ----
    qk_kernel<<<dim3(16, 16, NB), 256>>>(p_keys, p_quer, p_att);
    softmax_kernel<<<dim3(HW, NB), 256>>>(p_att);
    av_kernel<<<dim3(16, NB), 256>>>(p_att, p_vals, p_attv);

    // ---- GRN-O (aux = att_v), dual-input fused stage-1 ----
    mma_gemm_celu<<<gridS1, 256>>>(ul, sO, COC, goWi, p_attv, sV, VDIM, goWs,
                                   gobi, gobs, COC, p_h, sO);
    mma_gemm_celu<<<gridS2O, 256>>>(p_h, sO, COC, goWo, nullptr, 0, 0, nullptr,
                                    gobo, nullptr, 2 * COC, p_big, sBig);
    {
        const long t4 = (long)NB * COC * (HW / 4);
        gate_kernel<<<(unsigned)((t4 + 255) / 256), 256>>>(p_big, sBig, COC, ul, sO, out, sO, t4);
    }
}

// round 13
// speedup vs baseline: 1.7186x; 1.2849x over previous
#include <cuda_runtime.h>
#include <cuda_fp16.h>
#include <math.h>
#include <stdint.h>

#define NB 32
#define HW 1024

#define CKC 169   // x_ul_b channels
#define CQC 166   // ul_b channels
#define COC 160   // ul channels
#define KDIM 16
#define VDIM 80

#define BHH_ROWS 344
#define BHH_STRIDE ((long)BHH_ROWS * HW)

// ---------------- scratch (static device memory; no allocations) ----------------
__device__ float  g_cat [(size_t)NB * CKC * HW];       // x_ul_b [n,169,1024]; ul_b = view +3*HW
__device__ float  g_h   [(size_t)NB * CKC * HW];       // GRN hidden (f32)
__device__ __half g_bhH [(size_t)NB * BHH_ROWS * HW];  // celu'd pairs of hidden (fp16)
__device__ float  g_big [(size_t)NB * 2 * CKC * HW];   // GRN stage-2 raw [2C, hw]
__device__ float  g_gout[(size_t)NB * CKC * HW];       // GRN output
__device__ float  g_keys[(size_t)NB * KDIM * HW];
__device__ float  g_quer[(size_t)NB * KDIM * HW];
__device__ float  g_vals[(size_t)NB * VDIM * HW];
__device__ float  g_att [(size_t)NB * HW * HW];
__device__ float  g_attv[(size_t)NB * VDIM * HW];

__device__ __forceinline__ float eluf(float v) { return v > 0.f ? v : (expf(v) - 1.f); }

__device__ __forceinline__ void mma_f16(float* d, const unsigned* a, const unsigned* b) {
    asm volatile(
        "mma.sync.aligned.m16n8k16.row.col.f32.f16.f16.f32 "
        "{%0,%1,%2,%3}, {%4,%5,%6,%7}, {%8,%9}, {%0,%1,%2,%3};"
        : "+f"(d[0]), "+f"(d[1]), "+f"(d[2]), "+f"(d[3])
        : "r"(a[0]), "r"(a[1]), "r"(a[2]), "r"(a[3]), "r"(b[0]), "r"(b[1]));
}

// ---------------- concat inputs into [n,169,hw] ----------------
__global__ void build_cat_kernel(const float* __restrict__ x, const float* __restrict__ ul,
                                 const float* __restrict__ b, float* __restrict__ cat) {
    long idx = (long)blockIdx.x * blockDim.x + threadIdx.x;
    const long total = (long)NB * CKC * HW;
    if (idx >= total) return;
    int p = (int)(idx % HW);
    int c = (int)((idx / HW) % CKC);
    int n = (int)(idx / ((long)CKC * HW));
    float v;
    if (c < 3)        v = x [((long)n * 3   + c        ) * HW + p];
    else if (c < 163) v = ul[((long)n * 160 + (c - 3)  ) * HW + p];
    else              v = b [((long)n * 6   + (c - 163)) * HW + p];
    cat[idx] = v;
}

// ---------------- celu pairs: dst[c]=celu(src[c]), dst[c+C]=celu(-src[c]) (fp16) ----------------
__global__ void celu_pairs_kernel(const float* __restrict__ src, long srcStride, int C,
                                  __half* __restrict__ dst, long dstStride) {
    long idx = (long)blockIdx.x * blockDim.x + threadIdx.x;
    const long total = (long)NB * C * HW;
    if (idx >= total) return;
    int p = (int)(idx % HW);
    int c = (int)((idx / HW) % C);
    int n = (int)(idx / ((long)C * HW));
    const float v = src[(long)n * srcStride + (long)c * HW + p];
    __half* dn = dst + (long)n * dstStride;
    dn[(long)c * HW + p]       = __float2half(eluf(v));
    dn[(long)(c + C) * HW + p] = __float2half(eluf(-v));
}

// ============ FP16 MMA GEMM (R8/R11-proven): Out = W*concat_elu(X) [+ W2*concat_elu(X2)] + bias[+bias2]
// CTA tile: 64 out x 128 px, 256 threads = 8 warps (2 M x 4 N), warp tile 32x32, ping-pong smem.

#define SAH 34   // smem stride in halves

#define MG_LOAD_CHUNK(kk)                                                              \
    {                                                                                  \
        const float* Xs; const float* Ws; int Ci; long xs; int fb;                     \
        if ((kk) < nk1) { Xs = X;  Ws = W;  Ci = Cin;  xs = xStride;  fb = (kk) * 32; } \
        else            { Xs = X2; Ws = W2; Ci = Cin2; xs = x2Stride; fb = ((kk) - nk1) * 32; } \
        const int lim = 2 * Ci;                                                        \
        const int o = o0 + arow;                                                       \
        const bool oOK = o < Cout;                                                     \
        _Pragma("unroll")                                                              \
        for (int jj = 0; jj < 4; ++jj) {                                               \
            const int f = fb + afs + 2 * jj;                                           \
            float2 w2 = {0.f, 0.f};                                                    \
            if (oOK && f < lim)                                                        \
                w2 = *reinterpret_cast<const float2*>(&Ws[(long)o * lim + f]);         \
            areg[2 * jj] = w2.x; areg[2 * jj + 1] = w2.y;                              \
        }                                                                              \
        const float* Xn = Xs + (long)n * xs;                                           \
        _Pragma("unroll")                                                              \
        for (int j = 0; j < 16; ++j) {                                                 \
            const int ff = fb + bf0 + j;                                               \
            float v = 0.f;                                                             \
            if (ff < lim) {                                                            \
                const int c  = (ff < Ci) ? ff : (ff - Ci);                             \
                const float xv = Xn[(long)c * HW + p0 + bpx];                          \
                v = (ff < Ci) ? eluf(xv) : eluf(-xv);                                  \
            }                                                                          \
            breg[j] = v;                                                               \
        }                                                                              \
    }

#define MG_STORE_CHUNK(buf)                                                            \
    {                                                                                  \
        __half* pa = &sA[buf][arow * SAH + afs];                                       \
        _Pragma("unroll")                                                              \
        for (int jj = 0; jj < 4; ++jj)                                                 \
            *reinterpret_cast<__half2*>(pa + 2 * jj) =                                 \
                __floats2half2_rn(areg[2 * jj], areg[2 * jj + 1]);                     \
        __half* pb = &sB[buf][bpx * SAH + bf0];                                        \
        _Pragma("unroll")                                                              \
        for (int jj = 0; jj < 8; ++jj)                                                 \
            *reinterpret_cast<__half2*>(pb + 2 * jj) =                                 \
                __floats2half2_rn(breg[2 * jj], breg[2 * jj + 1]);                     \
    }

__global__ void __launch_bounds__(256)
mma_gemm_celu(const float* __restrict__ X, long xStride, int Cin,
              const float* __restrict__ W,
              const float* __restrict__ X2, long x2Stride, int Cin2,
              const float* __restrict__ W2,
              const float* __restrict__ bias, const float* __restrict__ bias2,
              int Cout, float* __restrict__ Out, long oStride) {
    __shared__ __align__(16) __half sA[2][64 * SAH];
    __shared__ __align__(16) __half sB[2][128 * SAH];
    const int tid  = threadIdx.x;
    const int warp = tid >> 5;
    const int lane = tid & 31;
    const int n  = blockIdx.y >> 3;
    const int p0 = (blockIdx.y & 7) * 128;
    const int o0 = blockIdx.x * 64;

    const int arow = tid >> 2;
    const int afs  = (tid & 3) * 8;
    const int bpx  = tid & 127;
    const int bf0  = (tid >> 7) * 16;
    const int m0w = (warp & 1) * 32;
    const int n0w = (warp >> 1) * 32;
    const int lq  = lane >> 2;
    const int lr  = lane & 3;

    const int nk1 = (2 * Cin + 31) >> 5;
    const int nk2 = W2 ? ((2 * Cin2 + 31) >> 5) : 0;
    const int nk  = nk1 + nk2;

    float areg[8], breg[16];
    float acc[2][4][4];
    #pragma unroll
    for (int mi = 0; mi < 2; ++mi)
        #pragma unroll
        for (int ni = 0; ni < 4; ++ni)
            #pragma unroll
            for (int e = 0; e < 4; ++e) acc[mi][ni][e] = 0.f;

    MG_LOAD_CHUNK(0);
    MG_STORE_CHUNK(0);
    __syncthreads();

    for (int k = 0; k < nk; ++k) {
        const int buf = k & 1;
        if (k + 1 < nk) MG_LOAD_CHUNK(k + 1);
        #pragma unroll
        for (int ks = 0; ks < 2; ++ks) {
            const int kb = ks * 16 + lr * 2;
            unsigned a[2][4], b[4][2];
            #pragma unroll
            for (int mi = 0; mi < 2; ++mi) {
                const __half* pa = &sA[buf][(m0w + mi * 16 + lq) * SAH + kb];
                a[mi][0] = *reinterpret_cast<const unsigned*>(pa);
                a[mi][1] = *reinterpret_cast<const unsigned*>(pa + 8 * SAH);
                a[mi][2] = *reinterpret_cast<const unsigned*>(pa + 8);
                a[mi][3] = *reinterpret_cast<const unsigned*>(pa + 8 * SAH + 8);
            }
            #pragma unroll
            for (int ni = 0; ni < 4; ++ni) {
                const __half* pb = &sB[buf][(n0w + ni * 8 + lq) * SAH + kb];
                b[ni][0] = *reinterpret_cast<const unsigned*>(pb);
                b[ni][1] = *reinterpret_cast<const unsigned*>(pb + 8);
            }
            #pragma unroll
            for (int mi = 0; mi < 2; ++mi)
                #pragma unroll
                for (int ni = 0; ni < 4; ++ni)
                    mma_f16(acc[mi][ni], a[mi], b[ni]);
        }
        if (k + 1 < nk) MG_STORE_CHUNK((k + 1) & 1);
        __syncthreads();
    }

    #pragma unroll
    for (int mi = 0; mi < 2; ++mi) {
        const int oa = o0 + m0w + mi * 16 + lq;
        const int ob = oa + 8;
        const float ba = (oa < Cout) ? (bias[oa] + (bias2 ? bias2[oa] : 0.f)) : 0.f;
        const float bb = (ob < Cout) ? (bias[ob] + (bias2 ? bias2[ob] : 0.f)) : 0.f;
        #pragma unroll
        for (int ni = 0; ni < 4; ++ni) {
            const int pp = p0 + n0w + ni * 8 + 2 * lr;
            if (oa < Cout) {
                float2 r = {acc[mi][ni][0] + ba, acc[mi][ni][1] + ba};
                *reinterpret_cast<float2*>(&Out[(long)n * oStride + (long)oa * HW + pp]) = r;
            }
            if (ob < Cout) {
                float2 r = {acc[mi][ni][2] + bb, acc[mi][ni][3] + bb};
                *reinterpret_cast<float2*>(&Out[(long)n * oStride + (long)ob * HW + pp]) = r;
            }
        }
    }
}

// ============ Stage-2 FP16-B GEMM: Out = W * BH + bias, BH = pre-celu'd fp16 rows [2*Cin] ============
// Identical tile structure; B loader is a pure half load (row = ff).

#define S2_LOAD_CHUNK(kk)                                                              \
    {                                                                                  \
        const int fb  = (kk) * 32;                                                     \
        const int lim = 2 * Cin;                                                       \
        const int o = o0 + arow;                                                       \
        const bool oOK = o < Cout;                                                     \
        _Pragma("unroll")                                                              \
        for (int jj = 0; jj < 4; ++jj) {                                               \
            const int f = fb + afs + 2 * jj;                                           \
            float2 w2 = {0.f, 0.f};                                                    \
            if (oOK && f < lim)                                                        \
                w2 = *reinterpret_cast<const float2*>(&W[(long)o * lim + f]);          \
            areg[2 * jj] = w2.x; areg[2 * jj + 1] = w2.y;                              \
        }                                                                              \
        const __half* Bn = BH + (long)n * bhStride;                                    \
        _Pragma("unroll")                                                              \
        for (int j = 0; j < 16; ++j) {                                                 \
            const int ff = fb + bf0 + j;                                               \
            hreg[j] = (ff < lim) ? Bn[(long)ff * HW + p0 + bpx]                        \
                                 : __ushort_as_half((unsigned short)0);                \
        }                                                                              \
    }

#define S2_STORE_CHUNK(buf)                                                            \
    {                                                                                  \
        __half* pa = &sA[buf][arow * SAH + afs];                                       \
        _Pragma("unroll")                                                              \
        for (int jj = 0; jj < 4; ++jj)                                                 \
            *reinterpret_cast<__half2*>(pa + 2 * jj) =                                 \
                __floats2half2_rn(areg[2 * jj], areg[2 * jj + 1]);                     \
        __half* pb = &sB[buf][bpx * SAH + bf0];                                        \
        _Pragma("unroll")                                                              \
        for (int j = 0; j < 16; ++j) pb[j] = hreg[j];                                  \
    }

__global__ void __launch_bounds__(256)
mma_gemm_s2h(const __half* __restrict__ BH, long bhStride, int Cin,
             const float* __restrict__ W, const float* __restrict__ bias,
             int Cout, float* __restrict__ Out, long oStride) {
    __shared__ __align__(16) __half sA[2][64 * SAH];
    __shared__ __align__(16) __half sB[2][128 * SAH];
    const int tid  = threadIdx.x;
    const int warp = tid >> 5;
    const int lane = tid & 31;
    const int n  = blockIdx.y >> 3;
    const int p0 = (blockIdx.y & 7) * 128;
    const int o0 = blockIdx.x * 64;

    const int arow = tid >> 2;
    const int afs  = (tid & 3) * 8;
    const int bpx  = tid & 127;
    const int bf0  = (tid >> 7) * 16;
    const int m0w = (warp & 1) * 32;
    const int n0w = (warp >> 1) * 32;
    const int lq  = lane >> 2;
    const int lr  = lane & 3;

    const int nk = (2 * Cin + 31) >> 5;

    float areg[8];
    __half hreg[16];
    float acc[2][4][4];
    #pragma unroll
    for (int mi = 0; mi < 2; ++mi)
        #pragma unroll
        for (int ni = 0; ni < 4; ++ni)
            #pragma unroll
            for (int e = 0; e < 4; ++e) acc[mi][ni][e] = 0.f;

    S2_LOAD_CHUNK(0);
    S2_STORE_CHUNK(0);
    __syncthreads();

    for (int k = 0; k < nk; ++k) {
        const int buf = k & 1;
        if (k + 1 < nk) S2_LOAD_CHUNK(k + 1);
        #pragma unroll
        for (int ks = 0; ks < 2; ++ks) {
            const int kb = ks * 16 + lr * 2;
            unsigned a[2][4], b[4][2];
            #pragma unroll
            for (int mi = 0; mi < 2; ++mi) {
                const __half* pa = &sA[buf][(m0w + mi * 16 + lq) * SAH + kb];
                a[mi][0] = *reinterpret_cast<const unsigned*>(pa);
                a[mi][1] = *reinterpret_cast<const unsigned*>(pa + 8 * SAH);
                a[mi][2] = *reinterpret_cast<const unsigned*>(pa + 8);
                a[mi][3] = *reinterpret_cast<const unsigned*>(pa + 8 * SAH + 8);
            }
            #pragma unroll
            for (int ni = 0; ni < 4; ++ni) {
                const __half* pb = &sB[buf][(n0w + ni * 8 + lq) * SAH + kb];
                b[ni][0] = *reinterpret_cast<const unsigned*>(pb);
                b[ni][1] = *reinterpret_cast<const unsigned*>(pb + 8);
            }
            #pragma unroll
            for (int mi = 0; mi < 2; ++mi)
                #pragma unroll
                for (int ni = 0; ni < 4; ++ni)
                    mma_f16(acc[mi][ni], a[mi], b[ni]);
        }
        if (k + 1 < nk) S2_STORE_CHUNK((k + 1) & 1);
        __syncthreads();
    }

    #pragma unroll
    for (int mi = 0; mi < 2; ++mi) {
        const int oa = o0 + m0w + mi * 16 + lq;
        const int ob = oa + 8;
        const float ba = (oa < Cout) ? bias[oa] : 0.f;
        const float bb = (ob < Cout) ? bias[ob] : 0.f;
        #pragma unroll
        for (int ni = 0; ni < 4; ++ni) {
            const int pp = p0 + n0w + ni * 8 + 2 * lr;
            if (oa < Cout) {
                float2 r = {acc[mi][ni][0] + ba, acc[mi][ni][1] + ba};
                *reinterpret_cast<float2*>(&Out[(long)n * oStride + (long)oa * HW + pp]) = r;
            }
            if (ob < Cout) {
                float2 r = {acc[mi][ni][2] + bb, acc[mi][ni][3] + bb};
                *reinterpret_cast<float2*>(&Out[(long)n * oStride + (long)ob * HW + pp]) = r;
            }
        }
    }
}

// ---------------- gate: out = Xres + ga*sigmoid(gb), ga=G[c], gb=G[c+C] ----------------
__global__ void __launch_bounds__(256)
gate_kernel(const float* __restrict__ G, long gStride, int C,
            const float* __restrict__ Xres, long xStride,
            float* __restrict__ Out, long oStride, long total4) {
    long idx = (long)blockIdx.x * blockDim.x + threadIdx.x;
    if (idx >= total4) return;
    const int perImg = C * (HW / 4);
    const int n = (int)(idx / perImg);
    const int r = (int)(idx - (long)n * perImg);
    const int c = r / (HW / 4);
    const int p4 = (r - c * (HW / 4)) * 4;
    const float4 ga = *reinterpret_cast<const float4*>(&G[(long)n * gStride + (long)c * HW + p4]);
    const float4 gb = *reinterpret_cast<const float4*>(&G[(long)n * gStride + (long)(c + C) * HW + p4]);
    const float4 xr = *reinterpret_cast<const float4*>(&Xres[(long)n * xStride + (long)c * HW + p4]);
    float4 o;
    o.x = xr.x + ga.x / (1.f + expf(-gb.x));
    o.y = xr.y + ga.y / (1.f + expf(-gb.y));
    o.z = xr.z + ga.z / (1.f + expf(-gb.z));
    o.w = xr.w + ga.w / (1.f + expf(-gb.w));
    *reinterpret_cast<float4*>(&Out[(long)n * oStride + (long)c * HW + p4]) = o;
}

// ---------------- small projection: Out[n, m0..m0+16, hw] = W*X + b ----------------
__global__ void __launch_bounds__(128)
proj16_kernel(const float* __restrict__ X, int Cin,
              const float* __restrict__ W, const float* __restrict__ bias,
              float* __restrict__ Out, int M) {
    __shared__ float sW[16 * 176];
    const int n  = blockIdx.y;
    const int m0 = blockIdx.z * 16;
    const int p  = blockIdx.x * 128 + threadIdx.x;
    for (int i = threadIdx.x; i < 16 * Cin; i += 128) {
        const int o = i / Cin, c = i - o * Cin;
        sW[o * 176 + c] = W[(long)(m0 + o) * Cin + c];
    }
    __syncthreads();
    const float* Xn = X + (long)n * Cin * HW;
    float acc[16];
    #pragma unroll
    for (int o = 0; o < 16; ++o) acc[o] = 0.f;
    #pragma unroll 4
    for (int c = 0; c < Cin; ++c) {
        const float v = Xn[(long)c * HW + p];
        #pragma unroll
        for (int o = 0; o < 16; ++o) acc[o] = fmaf(sW[o * 176 + c], v, acc[o]);
    }
    #pragma unroll
    for (int o = 0; o < 16; ++o)
        Out[((long)n * M + m0 + o) * HW + p] = acc[o] + bias[m0 + o];
}

// ---------------- presoftmax: S[n,q,k] = sum_j K[n,j,k]*Q[n,j,q]  (lower tiles only) ----------------
__global__ void qk_kernel(const float* __restrict__ Kt, const float* __restrict__ Qt,
                          float* __restrict__ S) {
    const int n  = blockIdx.z;
    const int q0 = blockIdx.y * 64;
    const int k0 = blockIdx.x * 64;
    if (k0 > q0) return;
    __shared__ float sK[16][64];
    __shared__ float sQ[16][64];
    const float* Kn = Kt + (long)n * KDIM * HW;
    const float* Qn = Qt + (long)n * KDIM * HW;
    const int p  = threadIdx.x & 63;
    const int jr = threadIdx.x >> 6;
    #pragma unroll
    for (int pass = 0; pass < 4; ++pass) {
        const int j = jr + pass * 4;
        sK[j][p] = Kn[(long)j * HW + k0 + p];
        sQ[j][p] = Qn[(long)j * HW + q0 + p];
    }
    __syncthreads();
    const int tx = threadIdx.x & 15, ty = threadIdx.x >> 4;
    float acc[4][4] = {};
    #pragma unroll
    for (int j = 0; j < 16; ++j) {
        const float4 q4 = *reinterpret_cast<const float4*>(&sQ[j][ty * 4]);
        const float4 k4 = *reinterpret_cast<const float4*>(&sK[j][tx * 4]);
        const float qr[4] = {q4.x, q4.y, q4.z, q4.w};
        const float kr[4] = {k4.x, k4.y, k4.z, k4.w};
        #pragma unroll
        for (int i = 0; i < 4; ++i)
            #pragma unroll
            for (int jj = 0; jj < 4; ++jj)
                acc[i][jj] = fmaf(qr[i], kr[jj], acc[i][jj]);
    }
    float* Sn = S + (long)n * HW * HW;
    #pragma unroll
    for (int i = 0; i < 4; ++i) {
        float4 r = {acc[i][0], acc[i][1], acc[i][2], acc[i][3]};
        *reinterpret_cast<float4*>(&Sn[(long)(q0 + ty * 4 + i) * HW + k0 + tx * 4]) = r;
    }
}

// ---------------- causal softmax per row (faithful semantics) ----------------
__global__ void softmax_kernel(float* __restrict__ S) {
    const int q = blockIdx.x;
    const int n = blockIdx.y;
    float* row = S + ((long)n * HW + (long)q) * HW;
    const int tid = threadIdx.x;  // 256
    __shared__ float red[256];

    float vals[4];
    float lmax = 0.f;
    #pragma unroll
    for (int i = 0; i < 4; ++i) {
        const int k = tid + i * 256;
        const float s = (k < q) ? row[k] : 0.f;
        vals[i] = s;
        if (k < q) lmax = fmaxf(lmax, s);
    }
    red[tid] = lmax;
    __syncthreads();
    for (int s2 = 128; s2 > 0; s2 >>= 1) {
        if (tid < s2) red[tid] = fmaxf(red[tid], red[tid + s2]);
        __syncthreads();
    }
    const float m = red[0];
    __syncthreads();

    float e[4];
    float lsum = 0.f;
    #pragma unroll
    for (int i = 0; i < 4; ++i) {
        const int k = tid + i * 256;
        e[i] = (k < q) ? expf(vals[i] - m) : 0.f;
        lsum += e[i];
    }
    red[tid] = lsum;
    __syncthreads();
    for (int s2 = 128; s2 > 0; s2 >>= 1) {
        if (tid < s2) red[tid] += red[tid + s2];
        __syncthreads();
    }
    const float Skept = red[0];
    const float D = Skept + (float)(HW - q) * expf(-m);
    const float inv = 1.f / (Skept + 1e-7f * D);
    const int kmax = (q & ~63) + 64;   // av only consumes k < roundup(q+1, 64)
    #pragma unroll
    for (int i = 0; i < 4; ++i) {
        const int k = tid + i * 256;
        if (k < kmax) row[k] = e[i] * inv;
    }
}

// ---------------- AV: Out[n,v,q] = sum_j Att[n,q,j] * V[n,v,j]  (K causally truncated) ----------------
__global__ void av_kernel(const float* __restrict__ Att, const float* __restrict__ V,
                          float* __restrict__ Out) {
    __shared__ float sV[16][80];
    __shared__ float sW[16][64];
    const int n  = blockIdx.y;
    const int q0 = blockIdx.x * 64;
    const float* An = Att + (long)n * HW * HW;
    const float* Vn = V + (long)n * VDIM * HW;
    const int tx = threadIdx.x & 15, ty = threadIdx.x >> 4;
    float acc[5][4] = {};
    const int jmax = min(HW, q0 + 64);

    for (int j0 = 0; j0 < jmax; j0 += 16) {
        for (int i = threadIdx.x; i < 16 * 80; i += 256) {
            const int v = i >> 4, jj = i & 15;
            sV[jj][v] = Vn[(long)v * HW + j0 + jj];
        }
        for (int i = threadIdx.x; i < 16 * 64; i += 256) {
            const int qq = i >> 4, jj = i & 15;
            sW[jj][qq] = An[(long)(q0 + qq) * HW + j0 + jj];
        }
        __syncthreads();
        #pragma unroll
        for (int jj = 0; jj < 16; ++jj) {
            const float4 w4 = *reinterpret_cast<const float4*>(&sW[jj][tx * 4]);
            const float wv[4] = {w4.x, w4.y, w4.z, w4.w};
            #pragma unroll
            for (int i = 0; i < 5; ++i) {
                const float vv = sV[jj][ty * 5 + i];
                #pragma unroll
                for (int j = 0; j < 4; ++j)
                    acc[i][j] = fmaf(vv, wv[j], acc[i][j]);
            }
        }
        __syncthreads();
    }
    #pragma unroll
    for (int i = 0; i < 5; ++i) {
        float4 r = {acc[i][0], acc[i][1], acc[i][2], acc[i][3]};
        *reinterpret_cast<float4*>(&Out[((long)n * VDIM + ty * 5 + i) * HW + q0 + tx * 4]) = r;
    }
}

// ---------------- launcher ----------------
extern "C" void kernel_launch(void* const* d_in, const int* in_sizes, int n_in,
                              void* d_out, int out_size) {
    (void)in_sizes; (void)n_in; (void)out_size;
    const float* x    = (const float*)d_in[0];
    const float* ul   = (const float*)d_in[1];
    const float* b    = (const float*)d_in[2];
    const float* gkWi = (const float*)d_in[3];
    const float* gkbi = (const float*)d_in[4];
    const float* gkWo = (const float*)d_in[5];
    const float* gkbo = (const float*)d_in[6];
    const float* gqWi = (const float*)d_in[7];
    const float* gqbi = (const float*)d_in[8];
    const float* gqWo = (const float*)d_in[9];
    const float* gqbo = (const float*)d_in[10];
    const float* gvWi = (const float*)d_in[11];
    const float* gvbi = (const float*)d_in[12];
    const float* gvWo = (const float*)d_in[13];
    const float* gvbo = (const float*)d_in[14];
    const float* nkW  = (const float*)d_in[15];
    const float* nkb  = (const float*)d_in[16];
    const float* nqW  = (const float*)d_in[17];
    const float* nqb  = (const float*)d_in[18];
    const float* nvW  = (const float*)d_in[19];
    const float* nvb  = (const float*)d_in[20];
    const float* goWi = (const float*)d_in[21];
    const float* gobi = (const float*)d_in[22];
    const float* goWs = (const float*)d_in[23];
    const float* gobs = (const float*)d_in[24];
    const float* goWo = (const float*)d_in[25];
    const float* gobo = (const float*)d_in[26];
    float* out = (float*)d_out;

    float *p_cat, *p_h, *p_big, *p_gout, *p_keys, *p_quer, *p_vals, *p_att, *p_attv;
    __half* p_bhH;
    cudaGetSymbolAddress((void**)&p_cat,  g_cat);
    cudaGetSymbolAddress((void**)&p_h,    g_h);
    cudaGetSymbolAddress((void**)&p_bhH,  g_bhH);
    cudaGetSymbolAddress((void**)&p_big,  g_big);
    cudaGetSymbolAddress((void**)&p_gout, g_gout);
    cudaGetSymbolAddress((void**)&p_keys, g_keys);
    cudaGetSymbolAddress((void**)&p_quer, g_quer);
    cudaGetSymbolAddress((void**)&p_vals, g_vals);
    cudaGetSymbolAddress((void**)&p_att,  g_att);
    cudaGetSymbolAddress((void**)&p_attv, g_attv);

    const long sCat = (long)CKC * HW;
    const long sQ   = (long)CQC * HW;
    const long sO   = (long)COC * HW;
    const long sV   = (long)VDIM * HW;
    const long sBig = (long)2 * CKC * HW;

    {
        const long total = (long)NB * CKC * HW;
        build_cat_kernel<<<(unsigned)((total + 255) / 256), 256>>>(x, ul, b, p_cat);
    }

    const dim3 gridS1(3, NB * 8);    // Cout<=169 -> 3 out-tiles of 64
    const dim3 gridS2K(6, NB * 8);   // Cout=338 -> 6
    const dim3 gridS2Q(6, NB * 8);   // Cout=332 -> 6
    const dim3 gridS2O(5, NB * 8);   // Cout=320 -> 5

    // ---- GRN-K -> keys ----
    mma_gemm_celu<<<gridS1, 256>>>(p_cat, sCat, CKC, gkWi, nullptr, 0, 0, nullptr,
                                   gkbi, nullptr, CKC, p_h, sCat);
    {
        const long t = (long)NB * CKC * HW;
        celu_pairs_kernel<<<(unsigned)((t + 255) / 256), 256>>>(p_h, sCat, CKC, p_bhH, BHH_STRIDE);
    }
    mma_gemm_s2h<<<gridS2K, 256>>>(p_bhH, BHH_STRIDE, CKC, gkWo, gkbo, 2 * CKC, p_big, sBig);
    {
        const long t4 = (long)NB * CKC * (HW / 4);
        gate_kernel<<<(unsigned)((t4 + 255) / 256), 256>>>(p_big, sBig, CKC, p_cat, sCat, p_gout, sCat, t4);
    }
    proj16_kernel<<<dim3(8, NB, 1), 128>>>(p_gout, CKC, nkW, nkb, p_keys, KDIM);

    // ---- GRN-Q -> queries (ul_b is a channel-offset view of cat) ----
    mma_gemm_celu<<<gridS1, 256>>>(p_cat + 3 * HW, sCat, CQC, gqWi, nullptr, 0, 0, nullptr,
                                   gqbi, nullptr, CQC, p_h, sQ);
    {
        const long t = (long)NB * CQC * HW;
        celu_pairs_kernel<<<(unsigned)((t + 255) / 256), 256>>>(p_h, sQ, CQC, p_bhH, BHH_STRIDE);
    }
    mma_gemm_s2h<<<gridS2Q, 256>>>(p_bhH, BHH_STRIDE, CQC, gqWo, gqbo, 2 * CQC, p_big, sBig);
    {
        const long t4 = (long)NB * CQC * (HW / 4);
        gate_kernel<<<(unsigned)((t4 + 255) / 256), 256>>>(p_big, sBig, CQC, p_cat + 3 * HW, sCat, p_gout, sQ, t4);
    }
    proj16_kernel<<<dim3(8, NB, 1), 128>>>(p_gout, CQC, nqW, nqb, p_quer, KDIM);

    // ---- GRN-V -> values ----
    mma_gemm_celu<<<gridS1, 256>>>(p_cat, sCat, CKC, gvWi, nullptr, 0, 0, nullptr,
                                   gvbi, nullptr, CKC, p_h, sCat);
    {
        const long t = (long)NB * CKC * HW;
        celu_pairs_kernel<<<(unsigned)((t + 255) / 256), 256>>>(p_h, sCat, CKC, p_bhH, BHH_STRIDE);
    }
    mma_gemm_s2h<<<gridS2K, 256>>>(p_bhH, BHH_STRIDE, CKC, gvWo, gvbo, 2 * CKC, p_big, sBig);
    {
        const long t4 = (long)NB * CKC * (HW / 4);
        gate_kernel<<<(unsigned)((t4 + 255) / 256), 256>>>(p_big, sBig, CKC, p_cat, sCat, p_gout, sCat, t4);
    }
    proj16_kernel<<<dim3(8, NB, 5), 128>>>(p_gout, CKC, nvW, nvb, p_vals, VDIM);

    // ---- attention ----
    qk_kernel<<<dim3(16, 16, NB), 256>>>(p_keys, p_quer, p_att);
    softmax_kernel<<<dim3(HW, NB), 256>>>(p_att);
    av_kernel<<<dim3(16, NB), 256>>>(p_att, p_vals, p_attv);

    // ---- GRN-O (aux = att_v), dual-input fused stage-1 ----
    mma_gemm_celu<<<gridS1, 256>>>(ul, sO, COC, goWi, p_attv, sV, VDIM, goWs,
                                   gobi, gobs, COC, p_h, sO);
    {
        const long t = (long)NB * COC * HW;
        celu_pairs_kernel<<<(unsigned)((t + 255) / 256), 256>>>(p_h, sO, COC, p_bhH, BHH_STRIDE);
    }
    mma_gemm_s2h<<<gridS2O, 256>>>(p_bhH, BHH_STRIDE, COC, goWo, gobo, 2 * COC, p_big, sBig);
    {
        const long t4 = (long)NB * COC * (HW / 4);
        gate_kernel<<<(unsigned)((t4 + 255) / 256), 256>>>(p_big, sBig, COC, ul, sO, out, sO, t4);
    }
}

// round 14
// speedup vs baseline: 2.0823x; 1.2116x over previous
#include <cuda_runtime.h>
#include <cuda_fp16.h>
#include <math.h>
#include <stdint.h>

#define NB 32
#define HW 1024

#define CKC 169   // x_ul_b channels
#define CQC 166   // ul_b channels
#define COC 160   // ul channels
#define KDIM 16
#define VDIM 80

#define BHA_ROWS 338
#define BHQ_ROWS 332
#define BHO_ROWS 480
#define BHH_ROWS 344
#define BHA_STRIDE ((long)BHA_ROWS * HW)
#define BHQ_STRIDE ((long)BHQ_ROWS * HW)
#define BHO_STRIDE ((long)BHO_ROWS * HW)
#define BHH_STRIDE ((long)BHH_ROWS * HW)

// ---------------- scratch (static device memory; no allocations) ----------------
__device__ float  g_cat [(size_t)NB * CKC * HW];        // x_ul_b f32 (residuals)
__device__ __half g_bhA [(size_t)NB * BHA_ROWS * HW];   // celu pairs of cat
__device__ __half g_bhQ [(size_t)NB * BHQ_ROWS * HW];   // celu pairs of ul_b view
__device__ __half g_bhO [(size_t)NB * BHO_ROWS * HW];   // celu pairs: ul (0..319), attv (320..479)
__device__ __half g_bhH [(size_t)NB * BHH_ROWS * HW];   // celu pairs of stage-1 hidden
__device__ float  g_h   [(size_t)NB * CKC * HW];        // stage-1 hidden f32
__device__ float  g_big [(size_t)NB * 2 * CKC * HW];    // stage-2 raw [2C, hw]
__device__ float  g_gout[(size_t)NB * CKC * HW];        // GRN output
__device__ float  g_keys[(size_t)NB * KDIM * HW];
__device__ float  g_quer[(size_t)NB * KDIM * HW];
__device__ float  g_vals[(size_t)NB * VDIM * HW];
__device__ float  g_att [(size_t)NB * HW * HW];
__device__ float  g_attv[(size_t)NB * VDIM * HW];

__device__ __forceinline__ float eluf(float v) { return v > 0.f ? v : (expf(v) - 1.f); }

__device__ __forceinline__ void mma_f16(float* d, const unsigned* a, const unsigned* b) {
    asm volatile(
        "mma.sync.aligned.m16n8k16.row.col.f32.f16.f16.f32 "
        "{%0,%1,%2,%3}, {%4,%5,%6,%7}, {%8,%9}, {%0,%1,%2,%3};"
        : "+f"(d[0]), "+f"(d[1]), "+f"(d[2]), "+f"(d[3])
        : "r"(a[0]), "r"(a[1]), "r"(a[2]), "r"(a[3]), "r"(b[0]), "r"(b[1]));
}

// ---------------- concat inputs into [n,169,hw] f32 + celu pairs fp16 ----------------
__global__ void build_cat_h_kernel(const float* __restrict__ x, const float* __restrict__ ul,
                                   const float* __restrict__ b, float* __restrict__ cat,
                                   __half* __restrict__ bh) {
    long idx = (long)blockIdx.x * blockDim.x + threadIdx.x;
    const long total = (long)NB * CKC * HW;
    if (idx >= total) return;
    int p = (int)(idx % HW);
    int c = (int)((idx / HW) % CKC);
    int n = (int)(idx / ((long)CKC * HW));
    float v;
    if (c < 3)        v = x [((long)n * 3   + c        ) * HW + p];
    else if (c < 163) v = ul[((long)n * 160 + (c - 3)  ) * HW + p];
    else              v = b [((long)n * 6   + (c - 163)) * HW + p];
    cat[idx] = v;
    __half* bn = bh + (long)n * BHA_STRIDE;
    bn[(long)c * HW + p]         = __float2half(eluf(v));
    bn[(long)(c + CKC) * HW + p] = __float2half(eluf(-v));
}

// ---------------- celu pairs: dst[c]=celu(src[c]), dst[c+C]=celu(-src[c]) (fp16) ----------------
__global__ void celu_pairs_kernel(const float* __restrict__ src, long srcStride, int C,
                                  __half* __restrict__ dst, long dstStride) {
    long idx = (long)blockIdx.x * blockDim.x + threadIdx.x;
    const long total = (long)NB * C * HW;
    if (idx >= total) return;
    int p = (int)(idx % HW);
    int c = (int)((idx / HW) % C);
    int n = (int)(idx / ((long)C * HW));
    const float v = src[(long)n * srcStride + (long)c * HW + p];
    __half* dn = dst + (long)n * dstStride;
    dn[(long)c * HW + p]       = __float2half(eluf(v));
    dn[(long)(c + C) * HW + p] = __float2half(eluf(-v));
}

#define SAH 34   // smem stride in halves

// ============ Stage-2 FP16-B GEMM (R13-validated, UNCHANGED): Out = W*BH + bias ============
#define S2_LOAD_CHUNK(kk)                                                              \
    {                                                                                  \
        const int fb  = (kk) * 32;                                                     \
        const int lim = 2 * Cin;                                                       \
        const int o = o0 + arow;                                                       \
        const bool oOK = o < Cout;                                                     \
        _Pragma("unroll")                                                              \
        for (int jj = 0; jj < 4; ++jj) {                                               \
            const int f = fb + afs + 2 * jj;                                           \
            float2 w2 = {0.f, 0.f};                                                    \
            if (oOK && f < lim)                                                        \
                w2 = *reinterpret_cast<const float2*>(&W[(long)o * lim + f]);          \
            areg[2 * jj] = w2.x; areg[2 * jj + 1] = w2.y;                              \
        }                                                                              \
        const __half* Bn = BH + (long)n * bhStride;                                    \
        _Pragma("unroll")                                                              \
        for (int j = 0; j < 16; ++j) {                                                 \
            const int ff = fb + bf0 + j;                                               \
            hreg[j] = (ff < lim) ? Bn[(long)ff * HW + p0 + bpx]                        \
                                 : __ushort_as_half((unsigned short)0);                \
        }                                                                              \
    }

#define S2_STORE_CHUNK(buf)                                                            \
    {                                                                                  \
        __half* pa = &sA[buf][arow * SAH + afs];                                       \
        _Pragma("unroll")                                                              \
        for (int jj = 0; jj < 4; ++jj)                                                 \
            *reinterpret_cast<__half2*>(pa + 2 * jj) =                                 \
                __floats2half2_rn(areg[2 * jj], areg[2 * jj + 1]);                     \
        __half* pb = &sB[buf][bpx * SAH + bf0];                                        \
        _Pragma("unroll")                                                              \
        for (int j = 0; j < 16; ++j) pb[j] = hreg[j];                                  \
    }

__global__ void __launch_bounds__(256)
mma_gemm_s2h(const __half* __restrict__ BH, long bhStride, int Cin,
             const float* __restrict__ W, const float* __restrict__ bias,
             int Cout, float* __restrict__ Out, long oStride) {
    __shared__ __align__(16) __half sA[2][64 * SAH];
    __shared__ __align__(16) __half sB[2][128 * SAH];
    const int tid  = threadIdx.x;
    const int warp = tid >> 5;
    const int lane = tid & 31;
    const int n  = blockIdx.y >> 3;
    const int p0 = (blockIdx.y & 7) * 128;
    const int o0 = blockIdx.x * 64;

    const int arow = tid >> 2;
    const int afs  = (tid & 3) * 8;
    const int bpx  = tid & 127;
    const int bf0  = (tid >> 7) * 16;
    const int m0w = (warp & 1) * 32;
    const int n0w = (warp >> 1) * 32;
    const int lq  = lane >> 2;
    const int lr  = lane & 3;

    const int nk = (2 * Cin + 31) >> 5;

    float areg[8];
    __half hreg[16];
    float acc[2][4][4];
    #pragma unroll
    for (int mi = 0; mi < 2; ++mi)
        #pragma unroll
        for (int ni = 0; ni < 4; ++ni)
            #pragma unroll
            for (int e = 0; e < 4; ++e) acc[mi][ni][e] = 0.f;

    S2_LOAD_CHUNK(0);
    S2_STORE_CHUNK(0);
    __syncthreads();

    for (int k = 0; k < nk; ++k) {
        const int buf = k & 1;
        if (k + 1 < nk) S2_LOAD_CHUNK(k + 1);
        #pragma unroll
        for (int ks = 0; ks < 2; ++ks) {
            const int kb = ks * 16 + lr * 2;
            unsigned a[2][4], b[4][2];
            #pragma unroll
            for (int mi = 0; mi < 2; ++mi) {
                const __half* pa = &sA[buf][(m0w + mi * 16 + lq) * SAH + kb];
                a[mi][0] = *reinterpret_cast<const unsigned*>(pa);
                a[mi][1] = *reinterpret_cast<const unsigned*>(pa + 8 * SAH);
                a[mi][2] = *reinterpret_cast<const unsigned*>(pa + 8);
                a[mi][3] = *reinterpret_cast<const unsigned*>(pa + 8 * SAH + 8);
            }
            #pragma unroll
            for (int ni = 0; ni < 4; ++ni) {
                const __half* pb = &sB[buf][(n0w + ni * 8 + lq) * SAH + kb];
                b[ni][0] = *reinterpret_cast<const unsigned*>(pb);
                b[ni][1] = *reinterpret_cast<const unsigned*>(pb + 8);
            }
            #pragma unroll
            for (int mi = 0; mi < 2; ++mi)
                #pragma unroll
                for (int ni = 0; ni < 4; ++ni)
                    mma_f16(acc[mi][ni], a[mi], b[ni]);
        }
        if (k + 1 < nk) S2_STORE_CHUNK((k + 1) & 1);
        __syncthreads();
    }

    #pragma unroll
    for (int mi = 0; mi < 2; ++mi) {
        const int oa = o0 + m0w + mi * 16 + lq;
        const int ob = oa + 8;
        const float ba = (oa < Cout) ? bias[oa] : 0.f;
        const float bb = (ob < Cout) ? bias[ob] : 0.f;
        #pragma unroll
        for (int ni = 0; ni < 4; ++ni) {
            const int pp = p0 + n0w + ni * 8 + 2 * lr;
            if (oa < Cout) {
                float2 r = {acc[mi][ni][0] + ba, acc[mi][ni][1] + ba};
                *reinterpret_cast<float2*>(&Out[(long)n * oStride + (long)oa * HW + pp]) = r;
            }
            if (ob < Cout) {
                float2 r = {acc[mi][ni][2] + bb, acc[mi][ni][3] + bb};
                *reinterpret_cast<float2*>(&Out[(long)n * oStride + (long)ob * HW + pp]) = r;
            }
        }
    }
}

// ============ Stage-1 FP16-B GEMM, dual-input capable: Out = W*BH [+ W2*BH2] + bias[+bias2] ============
#define H2_LOAD_CHUNK(kk)                                                              \
    {                                                                                  \
        const __half* Bs; long bst; int Ci, fb; const float* Ws;                       \
        if ((kk) < nk1) { Bs = BH;  bst = bhStride;  Ci = Cin;  Ws = W;  fb = (kk) * 32; } \
        else            { Bs = BH2; bst = bh2Stride; Ci = Cin2; Ws = W2; fb = ((kk) - nk1) * 32; } \
        const int lim = 2 * Ci;                                                        \
        const int o = o0 + arow;                                                       \
        const bool oOK = o < Cout;                                                     \
        _Pragma("unroll")                                                              \
        for (int jj = 0; jj < 4; ++jj) {                                               \
            const int f = fb + afs + 2 * jj;                                           \
            float2 w2 = {0.f, 0.f};                                                    \
            if (oOK && f < lim)                                                        \
                w2 = *reinterpret_cast<const float2*>(&Ws[(long)o * lim + f]);         \
            areg[2 * jj] = w2.x; areg[2 * jj + 1] = w2.y;                              \
        }                                                                              \
        const __half* Bn = Bs + (long)n * bst;                                         \
        _Pragma("unroll")                                                              \
        for (int j = 0; j < 16; ++j) {                                                 \
            const int ff = fb + bf0 + j;                                               \
            hreg[j] = (ff < lim) ? Bn[(long)ff * HW + p0 + bpx]                        \
                                 : __ushort_as_half((unsigned short)0);                \
        }                                                                              \
    }

__global__ void __launch_bounds__(256)
mma_gemm_h2(const __half* __restrict__ BH, long bhStride, int Cin,
            const float* __restrict__ W,
            const __half* __restrict__ BH2, long bh2Stride, int Cin2,
            const float* __restrict__ W2,
            const float* __restrict__ bias, const float* __restrict__ bias2,
            int Cout, float* __restrict__ Out, long oStride) {
    __shared__ __align__(16) __half sA[2][64 * SAH];
    __shared__ __align__(16) __half sB[2][128 * SAH];
    const int tid  = threadIdx.x;
    const int warp = tid >> 5;
    const int lane = tid & 31;
    const int n  = blockIdx.y >> 3;
    const int p0 = (blockIdx.y & 7) * 128;
    const int o0 = blockIdx.x * 64;

    const int arow = tid >> 2;
    const int afs  = (tid & 3) * 8;
    const int bpx  = tid & 127;
    const int bf0  = (tid >> 7) * 16;
    const int m0w = (warp & 1) * 32;
    const int n0w = (warp >> 1) * 32;
    const int lq  = lane >> 2;
    const int lr  = lane & 3;

    const int nk1 = (2 * Cin + 31) >> 5;
    const int nk2 = W2 ? ((2 * Cin2 + 31) >> 5) : 0;
    const int nk  = nk1 + nk2;

    float areg[8];
    __half hreg[16];
    float acc[2][4][4];
    #pragma unroll
    for (int mi = 0; mi < 2; ++mi)
        #pragma unroll
        for (int ni = 0; ni < 4; ++ni)
            #pragma unroll
            for (int e = 0; e < 4; ++e) acc[mi][ni][e] = 0.f;

    H2_LOAD_CHUNK(0);
    S2_STORE_CHUNK(0);
    __syncthreads();

    for (int k = 0; k < nk; ++k) {
        const int buf = k & 1;
        if (k + 1 < nk) H2_LOAD_CHUNK(k + 1);
        #pragma unroll
        for (int ks = 0; ks < 2; ++ks) {
            const int kb = ks * 16 + lr * 2;
            unsigned a[2][4], b[4][2];
            #pragma unroll
            for (int mi = 0; mi < 2; ++mi) {
                const __half* pa = &sA[buf][(m0w + mi * 16 + lq) * SAH + kb];
                a[mi][0] = *reinterpret_cast<const unsigned*>(pa);
                a[mi][1] = *reinterpret_cast<const unsigned*>(pa + 8 * SAH);
                a[mi][2] = *reinterpret_cast<const unsigned*>(pa + 8);
                a[mi][3] = *reinterpret_cast<const unsigned*>(pa + 8 * SAH + 8);
            }
            #pragma unroll
            for (int ni = 0; ni < 4; ++ni) {
                const __half* pb = &sB[buf][(n0w + ni * 8 + lq) * SAH + kb];
                b[ni][0] = *reinterpret_cast<const unsigned*>(pb);
                b[ni][1] = *reinterpret_cast<const unsigned*>(pb + 8);
            }
            #pragma unroll
            for (int mi = 0; mi < 2; ++mi)
                #pragma unroll
                for (int ni = 0; ni < 4; ++ni)
                    mma_f16(acc[mi][ni], a[mi], b[ni]);
        }
        if (k + 1 < nk) S2_STORE_CHUNK((k + 1) & 1);
        __syncthreads();
    }

    #pragma unroll
    for (int mi = 0; mi < 2; ++mi) {
        const int oa = o0 + m0w + mi * 16 + lq;
        const int ob = oa + 8;
        const float ba = (oa < Cout) ? (bias[oa] + (bias2 ? bias2[oa] : 0.f)) : 0.f;
        const float bb = (ob < Cout) ? (bias[ob] + (bias2 ? bias2[ob] : 0.f)) : 0.f;
        #pragma unroll
        for (int ni = 0; ni < 4; ++ni) {
            const int pp = p0 + n0w + ni * 8 + 2 * lr;
            if (oa < Cout) {
                float2 r = {acc[mi][ni][0] + ba, acc[mi][ni][1] + ba};
                *reinterpret_cast<float2*>(&Out[(long)n * oStride + (long)oa * HW + pp]) = r;
            }
            if (ob < Cout) {
                float2 r = {acc[mi][ni][2] + bb, acc[mi][ni][3] + bb};
                *reinterpret_cast<float2*>(&Out[(long)n * oStride + (long)ob * HW + pp]) = r;
            }
        }
    }
}

// ---------------- gate: out = Xres + ga*sigmoid(gb), ga=G[c], gb=G[c+C] ----------------
__global__ void __launch_bounds__(256)
gate_kernel(const float* __restrict__ G, long gStride, int C,
            const float* __restrict__ Xres, long xStride,
            float* __restrict__ Out, long oStride, long total4) {
    long idx = (long)blockIdx.x * blockDim.x + threadIdx.x;
    if (idx >= total4) return;
    const int perImg = C * (HW / 4);
    const int n = (int)(idx / perImg);
    const int r = (int)(idx - (long)n * perImg);
    const int c = r / (HW / 4);
    const int p4 = (r - c * (HW / 4)) * 4;
    const float4 ga = *reinterpret_cast<const float4*>(&G[(long)n * gStride + (long)c * HW + p4]);
    const float4 gb = *reinterpret_cast<const float4*>(&G[(long)n * gStride + (long)(c + C) * HW + p4]);
    const float4 xr = *reinterpret_cast<const float4*>(&Xres[(long)n * xStride + (long)c * HW + p4]);
    float4 o;
    o.x = xr.x + ga.x / (1.f + expf(-gb.x));
    o.y = xr.y + ga.y / (1.f + expf(-gb.y));
    o.z = xr.z + ga.z / (1.f + expf(-gb.z));
    o.w = xr.w + ga.w / (1.f + expf(-gb.w));
    *reinterpret_cast<float4*>(&Out[(long)n * oStride + (long)c * HW + p4]) = o;
}

// ---------------- small projection: Out[n, m0..m0+16, hw] = W*X + b ----------------
__global__ void __launch_bounds__(128)
proj16_kernel(const float* __restrict__ X, int Cin,
              const float* __restrict__ W, const float* __restrict__ bias,
              float* __restrict__ Out, int M) {
    __shared__ float sW[16 * 176];
    const int n  = blockIdx.y;
    const int m0 = blockIdx.z * 16;
    const int p  = blockIdx.x * 128 + threadIdx.x;
    for (int i = threadIdx.x; i < 16 * Cin; i += 128) {
        const int o = i / Cin, c = i - o * Cin;
        sW[o * 176 + c] = W[(long)(m0 + o) * Cin + c];
    }
    __syncthreads();
    const float* Xn = X + (long)n * Cin * HW;
    float acc[16];
    #pragma unroll
    for (int o = 0; o < 16; ++o) acc[o] = 0.f;
    #pragma unroll 4
    for (int c = 0; c < Cin; ++c) {
        const float v = Xn[(long)c * HW + p];
        #pragma unroll
        for (int o = 0; o < 16; ++o) acc[o] = fmaf(sW[o * 176 + c], v, acc[o]);
    }
    #pragma unroll
    for (int o = 0; o < 16; ++o)
        Out[((long)n * M + m0 + o) * HW + p] = acc[o] + bias[m0 + o];
}

// ---------------- presoftmax: S[n,q,k] = sum_j K[n,j,k]*Q[n,j,q]  (lower tiles only) ----------------
__global__ void qk_kernel(const float* __restrict__ Kt, const float* __restrict__ Qt,
                          float* __restrict__ S) {
    const int n  = blockIdx.z;
    const int q0 = blockIdx.y * 64;
    const int k0 = blockIdx.x * 64;
    if (k0 > q0) return;
    __shared__ float sK[16][64];
    __shared__ float sQ[16][64];
    const float* Kn = Kt + (long)n * KDIM * HW;
    const float* Qn = Qt + (long)n * KDIM * HW;
    const int p  = threadIdx.x & 63;
    const int jr = threadIdx.x >> 6;
    #pragma unroll
    for (int pass = 0; pass < 4; ++pass) {
        const int j = jr + pass * 4;
        sK[j][p] = Kn[(long)j * HW + k0 + p];
        sQ[j][p] = Qn[(long)j * HW + q0 + p];
    }
    __syncthreads();
    const int tx = threadIdx.x & 15, ty = threadIdx.x >> 4;
    float acc[4][4] = {};
    #pragma unroll
    for (int j = 0; j < 16; ++j) {
        const float4 q4 = *reinterpret_cast<const float4*>(&sQ[j][ty * 4]);
        const float4 k4 = *reinterpret_cast<const float4*>(&sK[j][tx * 4]);
        const float qr[4] = {q4.x, q4.y, q4.z, q4.w};
        const float kr[4] = {k4.x, k4.y, k4.z, k4.w};
        #pragma unroll
        for (int i = 0; i < 4; ++i)
            #pragma unroll
            for (int jj = 0; jj < 4; ++jj)
                acc[i][jj] = fmaf(qr[i], kr[jj], acc[i][jj]);
    }
    float* Sn = S + (long)n * HW * HW;
    #pragma unroll
    for (int i = 0; i < 4; ++i) {
        float4 r = {acc[i][0], acc[i][1], acc[i][2], acc[i][3]};
        *reinterpret_cast<float4*>(&Sn[(long)(q0 + ty * 4 + i) * HW + k0 + tx * 4]) = r;
    }
}

// ---------------- causal softmax per row (faithful semantics) ----------------
__global__ void softmax_kernel(float* __restrict__ S) {
    const int q = blockIdx.x;
    const int n = blockIdx.y;
    float* row = S + ((long)n * HW + (long)q) * HW;
    const int tid = threadIdx.x;  // 256
    __shared__ float red[256];

    float vals[4];
    float lmax = 0.f;
    #pragma unroll
    for (int i = 0; i < 4; ++i) {
        const int k = tid + i * 256;
        const float s = (k < q) ? row[k] : 0.f;
        vals[i] = s;
        if (k < q) lmax = fmaxf(lmax, s);
    }
    red[tid] = lmax;
    __syncthreads();
    for (int s2 = 128; s2 > 0; s2 >>= 1) {
        if (tid < s2) red[tid] = fmaxf(red[tid], red[tid + s2]);
        __syncthreads();
    }
    const float m = red[0];
    __syncthreads();

    float e[4];
    float lsum = 0.f;
    #pragma unroll
    for (int i = 0; i < 4; ++i) {
        const int k = tid + i * 256;
        e[i] = (k < q) ? expf(vals[i] - m) : 0.f;
        lsum += e[i];
    }
    red[tid] = lsum;
    __syncthreads();
    for (int s2 = 128; s2 > 0; s2 >>= 1) {
        if (tid < s2) red[tid] += red[tid + s2];
        __syncthreads();
    }
    const float Skept = red[0];
    const float D = Skept + (float)(HW - q) * expf(-m);
    const float inv = 1.f / (Skept + 1e-7f * D);
    const int kmax = (q & ~63) + 64;
    #pragma unroll
    for (int i = 0; i < 4; ++i) {
        const int k = tid + i * 256;
        if (k < kmax) row[k] = e[i] * inv;
    }
}

// ---------------- AV: Out[n,v,q] = sum_j Att[n,q,j] * V[n,v,j]  (K causally truncated) ----------------
__global__ void av_kernel(const float* __restrict__ Att, const float* __restrict__ V,
                          float* __restrict__ Out) {
    __shared__ float sV[16][80];
    __shared__ float sW[16][64];
    const int n  = blockIdx.y;
    const int q0 = blockIdx.x * 64;
    const float* An = Att + (long)n * HW * HW;
    const float* Vn = V + (long)n * VDIM * HW;
    const int tx = threadIdx.x & 15, ty = threadIdx.x >> 4;
    float acc[5][4] = {};
    const int jmax = min(HW, q0 + 64);

    for (int j0 = 0; j0 < jmax; j0 += 16) {
        for (int i = threadIdx.x; i < 16 * 80; i += 256) {
            const int v = i >> 4, jj = i & 15;
            sV[jj][v] = Vn[(long)v * HW + j0 + jj];
        }
        for (int i = threadIdx.x; i < 16 * 64; i += 256) {
            const int qq = i >> 4, jj = i & 15;
            sW[jj][qq] = An[(long)(q0 + qq) * HW + j0 + jj];
        }
        __syncthreads();
        #pragma unroll
        for (int jj = 0; jj < 16; ++jj) {
            const float4 w4 = *reinterpret_cast<const float4*>(&sW[jj][tx * 4]);
            const float wv[4] = {w4.x, w4.y, w4.z, w4.w};
            #pragma unroll
            for (int i = 0; i < 5; ++i) {
                const float vv = sV[jj][ty * 5 + i];
                #pragma unroll
                for (int j = 0; j < 4; ++j)
                    acc[i][j] = fmaf(vv, wv[j], acc[i][j]);
            }
        }
        __syncthreads();
    }
    #pragma unroll
    for (int i = 0; i < 5; ++i) {
        float4 r = {acc[i][0], acc[i][1], acc[i][2], acc[i][3]};
        *reinterpret_cast<float4*>(&Out[((long)n * VDIM + ty * 5 + i) * HW + q0 + tx * 4]) = r;
    }
}

// ---------------- launcher ----------------
extern "C" void kernel_launch(void* const* d_in, const int* in_sizes, int n_in,
                              void* d_out, int out_size) {
    (void)in_sizes; (void)n_in; (void)out_size;
    const float* x    = (const float*)d_in[0];
    const float* ul   = (const float*)d_in[1];
    const float* b    = (const float*)d_in[2];
    const float* gkWi = (const float*)d_in[3];
    const float* gkbi = (const float*)d_in[4];
    const float* gkWo = (const float*)d_in[5];
    const float* gkbo = (const float*)d_in[6];
    const float* gqWi = (const float*)d_in[7];
    const float* gqbi = (const float*)d_in[8];
    const float* gqWo = (const float*)d_in[9];
    const float* gqbo = (const float*)d_in[10];
    const float* gvWi = (const float*)d_in[11];
    const float* gvbi = (const float*)d_in[12];
    const float* gvWo = (const float*)d_in[13];
    const float* gvbo = (const float*)d_in[14];
    const float* nkW  = (const float*)d_in[15];
    const float* nkb  = (const float*)d_in[16];
    const float* nqW  = (const float*)d_in[17];
    const float* nqb  = (const float*)d_in[18];
    const float* nvW  = (const float*)d_in[19];
    const float* nvb  = (const float*)d_in[20];
    const float* goWi = (const float*)d_in[21];
    const float* gobi = (const float*)d_in[22];
    const float* goWs = (const float*)d_in[23];
    const float* gobs = (const float*)d_in[24];
    const float* goWo = (const float*)d_in[25];
    const float* gobo = (const float*)d_in[26];
    float* out = (float*)d_out;

    float *p_cat, *p_h, *p_big, *p_gout, *p_keys, *p_quer, *p_vals, *p_att, *p_attv;
    __half *p_bhA, *p_bhQ, *p_bhO, *p_bhH;
    cudaGetSymbolAddress((void**)&p_cat,  g_cat);
    cudaGetSymbolAddress((void**)&p_bhA,  g_bhA);
    cudaGetSymbolAddress((void**)&p_bhQ,  g_bhQ);
    cudaGetSymbolAddress((void**)&p_bhO,  g_bhO);
    cudaGetSymbolAddress((void**)&p_bhH,  g_bhH);
    cudaGetSymbolAddress((void**)&p_h,    g_h);
    cudaGetSymbolAddress((void**)&p_big,  g_big);
    cudaGetSymbolAddress((void**)&p_gout, g_gout);
    cudaGetSymbolAddress((void**)&p_keys, g_keys);
    cudaGetSymbolAddress((void**)&p_quer, g_quer);
    cudaGetSymbolAddress((void**)&p_vals, g_vals);
    cudaGetSymbolAddress((void**)&p_att,  g_att);
    cudaGetSymbolAddress((void**)&p_attv, g_attv);

    const long sCat = (long)CKC * HW;
    const long sQ   = (long)CQC * HW;
    const long sO   = (long)COC * HW;
    const long sV   = (long)VDIM * HW;
    const long sBig = (long)2 * CKC * HW;

    {
        const long total = (long)NB * CKC * HW;
        build_cat_h_kernel<<<(unsigned)((total + 255) / 256), 256>>>(x, ul, b, p_cat, p_bhA);
    }
    {   // Q-view pairs (dedicated buffer, no offsets in GEMM)
        const long t = (long)NB * CQC * HW;
        celu_pairs_kernel<<<(unsigned)((t + 255) / 256), 256>>>(p_cat + 3 * HW, sCat, CQC, p_bhQ, BHQ_STRIDE);
    }

    const dim3 gridS1(3, NB * 8);    // Cout<=169
    const dim3 gridS2K(6, NB * 8);   // 338
    const dim3 gridS2Q(6, NB * 8);   // 332
    const dim3 gridS2O(5, NB * 8);   // 320

    // ---- GRN-K -> keys ----
    mma_gemm_h2<<<gridS1, 256>>>(p_bhA, BHA_STRIDE, CKC, gkWi,
                                 nullptr, 0, 0, nullptr, gkbi, nullptr,
                                 CKC, p_h, sCat);
    {
        const long t = (long)NB * CKC * HW;
        celu_pairs_kernel<<<(unsigned)((t + 255) / 256), 256>>>(p_h, sCat, CKC, p_bhH, BHH_STRIDE);
    }
    mma_gemm_s2h<<<gridS2K, 256>>>(p_bhH, BHH_STRIDE, CKC, gkWo, gkbo, 2 * CKC, p_big, sBig);
    {
        const long t4 = (long)NB * CKC * (HW / 4);
        gate_kernel<<<(unsigned)((t4 + 255) / 256), 256>>>(p_big, sBig, CKC, p_cat, sCat, p_gout, sCat, t4);
    }
    proj16_kernel<<<dim3(8, NB, 1), 128>>>(p_gout, CKC, nkW, nkb, p_keys, KDIM);

    // ---- GRN-Q -> queries ----
    mma_gemm_h2<<<gridS1, 256>>>(p_bhQ, BHQ_STRIDE, CQC, gqWi,
                                 nullptr, 0, 0, nullptr, gqbi, nullptr,
                                 CQC, p_h, sQ);
    {
        const long t = (long)NB * CQC * HW;
        celu_pairs_kernel<<<(unsigned)((t + 255) / 256), 256>>>(p_h, sQ, CQC, p_bhH, BHH_STRIDE);
    }
    mma_gemm_s2h<<<gridS2Q, 256>>>(p_bhH, BHH_STRIDE, CQC, gqWo, gqbo, 2 * CQC, p_big, sBig);
    {
        const long t4 = (long)NB * CQC * (HW / 4);
        gate_kernel<<<(unsigned)((t4 + 255) / 256), 256>>>(p_big, sBig, CQC, p_cat + 3 * HW, sCat, p_gout, sQ, t4);
    }
    proj16_kernel<<<dim3(8, NB, 1), 128>>>(p_gout, CQC, nqW, nqb, p_quer, KDIM);

    // ---- GRN-V -> values ----
    mma_gemm_h2<<<gridS1, 256>>>(p_bhA, BHA_STRIDE, CKC, gvWi,
                                 nullptr, 0, 0, nullptr, gvbi, nullptr,
                                 CKC, p_h, sCat);
    {
        const long t = (long)NB * CKC * HW;
        celu_pairs_kernel<<<(unsigned)((t + 255) / 256), 256>>>(p_h, sCat, CKC, p_bhH, BHH_STRIDE);
    }
    mma_gemm_s2h<<<gridS2K, 256>>>(p_bhH, BHH_STRIDE, CKC, gvWo, gvbo, 2 * CKC, p_big, sBig);
    {
        const long t4 = (long)NB * CKC * (HW / 4);
        gate_kernel<<<(unsigned)((t4 + 255) / 256), 256>>>(p_big, sBig, CKC, p_cat, sCat, p_gout, sCat, t4);
    }
    proj16_kernel<<<dim3(8, NB, 5), 128>>>(p_gout, CKC, nvW, nvb, p_vals, VDIM);

    // ---- attention ----
    qk_kernel<<<dim3(16, 16, NB), 256>>>(p_keys, p_quer, p_att);
    softmax_kernel<<<dim3(HW, NB), 256>>>(p_att);
    av_kernel<<<dim3(16, NB), 256>>>(p_att, p_vals, p_attv);

    // ---- GRN-O: celu(ul) + celu(attv) pairs -> dual stage-1 -> stage-2 -> gate -> out ----
    {
        const long tUL = (long)NB * COC * HW;
        celu_pairs_kernel<<<(unsigned)((tUL + 255) / 256), 256>>>(ul, sO, COC, p_bhO, BHO_STRIDE);
        const long tAV = (long)NB * VDIM * HW;
        celu_pairs_kernel<<<(unsigned)((tAV + 255) / 256), 256>>>(p_attv, sV, VDIM,
                                                                  p_bhO + (long)320 * HW, BHO_STRIDE);
    }
    mma_gemm_h2<<<gridS1, 256>>>(p_bhO, BHO_STRIDE, COC, goWi,
                                 p_bhO + (long)320 * HW, BHO_STRIDE, VDIM, goWs,
                                 gobi, gobs, COC, p_h, sO);
    {
        const long t = (long)NB * COC * HW;
        celu_pairs_kernel<<<(unsigned)((t + 255) / 256), 256>>>(p_h, sO, COC, p_bhH, BHH_STRIDE);
    }
    mma_gemm_s2h<<<gridS2O, 256>>>(p_bhH, BHH_STRIDE, COC, goWo, gobo, 2 * COC, p_big, sBig);
    {
        const long t4 = (long)NB * COC * (HW / 4);
        gate_kernel<<<(unsigned)((t4 + 255) / 256), 256>>>(p_big, sBig, COC, ul, sO, out, sO, t4);
    }
}

// round 16
// speedup vs baseline: 2.2799x; 1.0949x over previous
#include <cuda_runtime.h>
#include <cuda_fp16.h>
#include <math.h>
#include <stdint.h>

#define NB 32
#define HW 1024

#define CKC 169   // x_ul_b channels
#define CQC 166   // ul_b channels
#define COC 160   // ul channels
#define KDIM 16
#define VDIM 80

#define BHA_ROWS 338
#define BHQ_ROWS 332
#define BHO_ROWS 480
#define BHH_ROWS 344
#define BHA_STRIDE ((long)BHA_ROWS * HW)
#define BHQ_STRIDE ((long)BHQ_ROWS * HW)
#define BHO_STRIDE ((long)BHO_ROWS * HW)
#define BHH_STRIDE ((long)BHH_ROWS * HW)

// ---------------- scratch (static device memory; no allocations) ----------------
__device__ float  g_cat [(size_t)NB * CKC * HW];        // x_ul_b f32 (residuals)
__device__ __half g_bhA [(size_t)NB * BHA_ROWS * HW];   // celu pairs of cat
__device__ __half g_bhQ [(size_t)NB * BHQ_ROWS * HW];   // celu pairs of ul_b view
__device__ __half g_bhO [(size_t)NB * BHO_ROWS * HW];   // celu pairs: ul (0..319), attv (320..479)
__device__ __half g_bhH [(size_t)NB * BHH_ROWS * HW];   // celu pairs of stage-1 hidden
__device__ float  g_big [(size_t)NB * 2 * CKC * HW];    // stage-2 raw [2C, hw]
__device__ float  g_gout[(size_t)NB * CKC * HW];        // GRN output
__device__ float  g_keys[(size_t)NB * KDIM * HW];
__device__ float  g_quer[(size_t)NB * KDIM * HW];
__device__ float  g_vals[(size_t)NB * VDIM * HW];
__device__ float  g_att [(size_t)NB * HW * HW];
__device__ float  g_attv[(size_t)NB * VDIM * HW];

__device__ __forceinline__ float eluf(float v) { return v > 0.f ? v : (expf(v) - 1.f); }

__device__ __forceinline__ void mma_f16(float* d, const unsigned* a, const unsigned* b) {
    asm volatile(
        "mma.sync.aligned.m16n8k16.row.col.f32.f16.f16.f32 "
        "{%0,%1,%2,%3}, {%4,%5,%6,%7}, {%8,%9}, {%0,%1,%2,%3};"
        : "+f"(d[0]), "+f"(d[1]), "+f"(d[2]), "+f"(d[3])
        : "r"(a[0]), "r"(a[1]), "r"(a[2]), "r"(a[3]), "r"(b[0]), "r"(b[1]));
}

// ---------------- concat inputs into [n,169,hw] f32 + celu pairs fp16 ----------------
__global__ void build_cat_h_kernel(const float* __restrict__ x, const float* __restrict__ ul,
                                   const float* __restrict__ b, float* __restrict__ cat,
                                   __half* __restrict__ bh) {
    long idx = (long)blockIdx.x * blockDim.x + threadIdx.x;
    const long total = (long)NB * CKC * HW;
    if (idx >= total) return;
    int p = (int)(idx % HW);
    int c = (int)((idx / HW) % CKC);
    int n = (int)(idx / ((long)CKC * HW));
    float v;
    if (c < 3)        v = x [((long)n * 3   + c        ) * HW + p];
    else if (c < 163) v = ul[((long)n * 160 + (c - 3)  ) * HW + p];
    else              v = b [((long)n * 6   + (c - 163)) * HW + p];
    cat[idx] = v;
    __half* bn = bh + (long)n * BHA_STRIDE;
    bn[(long)c * HW + p]         = __float2half(eluf(v));
    bn[(long)(c + CKC) * HW + p] = __float2half(eluf(-v));
}

// ---------------- celu pairs (vectorized x4): dst[c]=celu(src[c]), dst[c+C]=celu(-src[c]) ----------------
__global__ void __launch_bounds__(256)
celu_pairs4_kernel(const float* __restrict__ src, long srcStride, int C,
                   __half* __restrict__ dst, long dstStride) {
    const long total4 = (long)NB * C * (HW / 4);
    long idx = (long)blockIdx.x * blockDim.x + threadIdx.x;
    if (idx >= total4) return;
    const int perImg = C * (HW / 4);
    const int n = (int)(idx / perImg);
    const int r = (int)(idx - (long)n * perImg);
    const int c = r >> 8;               // HW/4 = 256
    const int p4 = (r & 255) * 4;
    const float4 v = *reinterpret_cast<const float4*>(&src[(long)n * srcStride + (long)c * HW + p4]);
    __half* dn = dst + (long)n * dstStride;
    __half2 hp[2], hm[2];
    hp[0] = __floats2half2_rn(eluf(v.x), eluf(v.y));
    hp[1] = __floats2half2_rn(eluf(v.z), eluf(v.w));
    hm[0] = __floats2half2_rn(eluf(-v.x), eluf(-v.y));
    hm[1] = __floats2half2_rn(eluf(-v.z), eluf(-v.w));
    *reinterpret_cast<uint2*>(&dn[(long)c * HW + p4])       = *reinterpret_cast<uint2*>(hp);
    *reinterpret_cast<uint2*>(&dn[(long)(c + C) * HW + p4]) = *reinterpret_cast<uint2*>(hm);
}

#define SAH 34   // smem stride in halves

// ============ Stage-2 FP16-B GEMM (R13-validated, UNCHANGED): Out = W*BH + bias ============
#define S2_LOAD_CHUNK(kk)                                                              \
    {                                                                                  \
        const int fb  = (kk) * 32;                                                     \
        const int lim = 2 * Cin;                                                       \
        const int o = o0 + arow;                                                       \
        const bool oOK = o < Cout;                                                     \
        _Pragma("unroll")                                                              \
        for (int jj = 0; jj < 4; ++jj) {                                               \
            const int f = fb + afs + 2 * jj;                                           \
            float2 w2 = {0.f, 0.f};                                                    \
            if (oOK && f < lim)                                                        \
                w2 = *reinterpret_cast<const float2*>(&W[(long)o * lim + f]);          \
            areg[2 * jj] = w2.x; areg[2 * jj + 1] = w2.y;                              \
        }                                                                              \
        const __half* Bn = BH + (long)n * bhStride;                                    \
        _Pragma("unroll")                                                              \
        for (int j = 0; j < 16; ++j) {                                                 \
            const int ff = fb + bf0 + j;                                               \
            hreg[j] = (ff < lim) ? Bn[(long)ff * HW + p0 + bpx]                        \
                                 : __ushort_as_half((unsigned short)0);                \
        }                                                                              \
    }

#define S2_STORE_CHUNK(buf)                                                            \
    {                                                                                  \
        __half* pa = &sA[buf][arow * SAH + afs];                                       \
        _Pragma("unroll")                                                              \
        for (int jj = 0; jj < 4; ++jj)                                                 \
            *reinterpret_cast<__half2*>(pa + 2 * jj) =                                 \
                __floats2half2_rn(areg[2 * jj], areg[2 * jj + 1]);                     \
        __half* pb = &sB[buf][bpx * SAH + bf0];                                        \
        _Pragma("unroll")                                                              \
        for (int j = 0; j < 16; ++j) pb[j] = hreg[j];                                  \
    }

__global__ void __launch_bounds__(256)
mma_gemm_s2h(const __half* __restrict__ BH, long bhStride, int Cin,
             const float* __restrict__ W, const float* __restrict__ bias,
             int Cout, float* __restrict__ Out, long oStride) {
    __shared__ __align__(16) __half sA[2][64 * SAH];
    __shared__ __align__(16) __half sB[2][128 * SAH];
    const int tid  = threadIdx.x;
    const int warp = tid >> 5;
    const int lane = tid & 31;
    const int n  = blockIdx.y >> 3;
    const int p0 = (blockIdx.y & 7) * 128;
    const int o0 = blockIdx.x * 64;

    const int arow = tid >> 2;
    const int afs  = (tid & 3) * 8;
    const int bpx  = tid & 127;
    const int bf0  = (tid >> 7) * 16;
    const int m0w = (warp & 1) * 32;
    const int n0w = (warp >> 1) * 32;
    const int lq  = lane >> 2;
    const int lr  = lane & 3;

    const int nk = (2 * Cin + 31) >> 5;

    float areg[8];
    __half hreg[16];
    float acc[2][4][4];
    #pragma unroll
    for (int mi = 0; mi < 2; ++mi)
        #pragma unroll
        for (int ni = 0; ni < 4; ++ni)
            #pragma unroll
            for (int e = 0; e < 4; ++e) acc[mi][ni][e] = 0.f;

    S2_LOAD_CHUNK(0);
    S2_STORE_CHUNK(0);
    __syncthreads();

    for (int k = 0; k < nk; ++k) {
        const int buf = k & 1;
        if (k + 1 < nk) S2_LOAD_CHUNK(k + 1);
        #pragma unroll
        for (int ks = 0; ks < 2; ++ks) {
            const int kb = ks * 16 + lr * 2;
            unsigned a[2][4], b[4][2];
            #pragma unroll
            for (int mi = 0; mi < 2; ++mi) {
                const __half* pa = &sA[buf][(m0w + mi * 16 + lq) * SAH + kb];
                a[mi][0] = *reinterpret_cast<const unsigned*>(pa);
                a[mi][1] = *reinterpret_cast<const unsigned*>(pa + 8 * SAH);
                a[mi][2] = *reinterpret_cast<const unsigned*>(pa + 8);
                a[mi][3] = *reinterpret_cast<const unsigned*>(pa + 8 * SAH + 8);
            }
            #pragma unroll
            for (int ni = 0; ni < 4; ++ni) {
                const __half* pb = &sB[buf][(n0w + ni * 8 + lq) * SAH + kb];
                b[ni][0] = *reinterpret_cast<const unsigned*>(pb);
                b[ni][1] = *reinterpret_cast<const unsigned*>(pb + 8);
            }
            #pragma unroll
            for (int mi = 0; mi < 2; ++mi)
                #pragma unroll
                for (int ni = 0; ni < 4; ++ni)
                    mma_f16(acc[mi][ni], a[mi], b[ni]);
        }
        if (k + 1 < nk) S2_STORE_CHUNK((k + 1) & 1);
        __syncthreads();
    }

    #pragma unroll
    for (int mi = 0; mi < 2; ++mi) {
        const int oa = o0 + m0w + mi * 16 + lq;
        const int ob = oa + 8;
        const float ba = (oa < Cout) ? bias[oa] : 0.f;
        const float bb = (ob < Cout) ? bias[ob] : 0.f;
        #pragma unroll
        for (int ni = 0; ni < 4; ++ni) {
            const int pp = p0 + n0w + ni * 8 + 2 * lr;
            if (oa < Cout) {
                float2 r = {acc[mi][ni][0] + ba, acc[mi][ni][1] + ba};
                *reinterpret_cast<float2*>(&Out[(long)n * oStride + (long)oa * HW + pp]) = r;
            }
            if (ob < Cout) {
                float2 r = {acc[mi][ni][2] + bb, acc[mi][ni][3] + bb};
                *reinterpret_cast<float2*>(&Out[(long)n * oStride + (long)ob * HW + pp]) = r;
            }
        }
    }
}

// ============ Stage-1 FP16-B GEMM with celu-pair epilogue: BHout = celu(+/-(W*BH[+W2*BH2]+bias)) ============
#define H2_LOAD_CHUNK(kk)                                                              \
    {                                                                                  \
        const __half* Bs; long bst; int Ci, fb; const float* Ws;                       \
        if ((kk) < nk1) { Bs = BH;  bst = bhStride;  Ci = Cin;  Ws = W;  fb = (kk) * 32; } \
        else            { Bs = BH2; bst = bh2Stride; Ci = Cin2; Ws = W2; fb = ((kk) - nk1) * 32; } \
        const int lim = 2 * Ci;                                                        \
        const int o = o0 + arow;                                                       \
        const bool oOK = o < Cout;                                                     \
        _Pragma("unroll")                                                              \
        for (int jj = 0; jj < 4; ++jj) {                                               \
            const int f = fb + afs + 2 * jj;                                           \
            float2 w2 = {0.f, 0.f};                                                    \
            if (oOK && f < lim)                                                        \
                w2 = *reinterpret_cast<const float2*>(&Ws[(long)o * lim + f]);         \
            areg[2 * jj] = w2.x; areg[2 * jj + 1] = w2.y;                              \
        }                                                                              \
        const __half* Bn = Bs + (long)n * bst;                                         \
        _Pragma("unroll")                                                              \
        for (int j = 0; j < 16; ++j) {                                                 \
            const int ff = fb + bf0 + j;                                               \
            hreg[j] = (ff < lim) ? Bn[(long)ff * HW + p0 + bpx]                        \
                                 : __ushort_as_half((unsigned short)0);                \
        }                                                                              \
    }

__global__ void __launch_bounds__(256)
mma_gemm_h2e(const __half* __restrict__ BH, long bhStride, int Cin,
             const float* __restrict__ W,
             const __half* __restrict__ BH2, long bh2Stride, int Cin2,
             const float* __restrict__ W2,
             const float* __restrict__ bias, const float* __restrict__ bias2,
             int Cout, __half* __restrict__ OutH, long oStrideH) {
    __shared__ __align__(16) __half sA[2][64 * SAH];
    __shared__ __align__(16) __half sB[2][128 * SAH];
    const int tid  = threadIdx.x;
    const int warp = tid >> 5;
    const int lane = tid & 31;
    const int n  = blockIdx.y >> 3;
    const int p0 = (blockIdx.y & 7) * 128;
    const int o0 = blockIdx.x * 64;

    const int arow = tid >> 2;
    const int afs  = (tid & 3) * 8;
    const int bpx  = tid & 127;
    const int bf0  = (tid >> 7) * 16;
    const int m0w = (warp & 1) * 32;
    const int n0w = (warp >> 1) * 32;
    const int lq  = lane >> 2;
    const int lr  = lane & 3;

    const int nk1 = (2 * Cin + 31) >> 5;
    const int nk2 = W2 ? ((2 * Cin2 + 31) >> 5) : 0;
    const int nk  = nk1 + nk2;

    float areg[8];
    __half hreg[16];
    float acc[2][4][4];
    #pragma unroll
    for (int mi = 0; mi < 2; ++mi)
        #pragma unroll
        for (int ni = 0; ni < 4; ++ni)
            #pragma unroll
            for (int e = 0; e < 4; ++e) acc[mi][ni][e] = 0.f;

    H2_LOAD_CHUNK(0);
    S2_STORE_CHUNK(0);
    __syncthreads();

    for (int k = 0; k < nk; ++k) {
        const int buf = k & 1;
        if (k + 1 < nk) H2_LOAD_CHUNK(k + 1);
        #pragma unroll
        for (int ks = 0; ks < 2; ++ks) {
            const int kb = ks * 16 + lr * 2;
            unsigned a[2][4], b[4][2];
            #pragma unroll
            for (int mi = 0; mi < 2; ++mi) {
                const __half* pa = &sA[buf][(m0w + mi * 16 + lq) * SAH + kb];
                a[mi][0] = *reinterpret_cast<const unsigned*>(pa);
                a[mi][1] = *reinterpret_cast<const unsigned*>(pa + 8 * SAH);
                a[mi][2] = *reinterpret_cast<const unsigned*>(pa + 8);
                a[mi][3] = *reinterpret_cast<const unsigned*>(pa + 8 * SAH + 8);
            }
            #pragma unroll
            for (int ni = 0; ni < 4; ++ni) {
                const __half* pb = &sB[buf][(n0w + ni * 8 + lq) * SAH + kb];
                b[ni][0] = *reinterpret_cast<const unsigned*>(pb);
                b[ni][1] = *reinterpret_cast<const unsigned*>(pb + 8);
            }
            #pragma unroll
            for (int mi = 0; mi < 2; ++mi)
                #pragma unroll
                for (int ni = 0; ni < 4; ++ni)
                    mma_f16(acc[mi][ni], a[mi], b[ni]);
        }
        if (k + 1 < nk) S2_STORE_CHUNK((k + 1) & 1);
        __syncthreads();
    }

    // epilogue: write celu pairs (rows o and o+Cout) as fp16
    __half* dn = OutH + (long)n * oStrideH;
    #pragma unroll
    for (int mi = 0; mi < 2; ++mi) {
        const int oa = o0 + m0w + mi * 16 + lq;
        const int ob = oa + 8;
        const float ba = (oa < Cout) ? (bias[oa] + (bias2 ? bias2[oa] : 0.f)) : 0.f;
        const float bb = (ob < Cout) ? (bias[ob] + (bias2 ? bias2[ob] : 0.f)) : 0.f;
        #pragma unroll
        for (int ni = 0; ni < 4; ++ni) {
            const int pp = p0 + n0w + ni * 8 + 2 * lr;
            if (oa < Cout) {
                const float v0 = acc[mi][ni][0] + ba, v1 = acc[mi][ni][1] + ba;
                *reinterpret_cast<__half2*>(&dn[(long)oa * HW + pp]) =
                    __floats2half2_rn(eluf(v0), eluf(v1));
                *reinterpret_cast<__half2*>(&dn[(long)(oa + Cout) * HW + pp]) =
                    __floats2half2_rn(eluf(-v0), eluf(-v1));
            }
            if (ob < Cout) {
                const float v0 = acc[mi][ni][2] + bb, v1 = acc[mi][ni][3] + bb;
                *reinterpret_cast<__half2*>(&dn[(long)ob * HW + pp]) =
                    __floats2half2_rn(eluf(v0), eluf(v1));
                *reinterpret_cast<__half2*>(&dn[(long)(ob + Cout) * HW + pp]) =
                    __floats2half2_rn(eluf(-v0), eluf(-v1));
            }
        }
    }
}

// ---------------- gate: out = Xres + ga*sigmoid(gb), ga=G[c], gb=G[c+C] ----------------
__global__ void __launch_bounds__(256)
gate_kernel(const float* __restrict__ G, long gStride, int C,
            const float* __restrict__ Xres, long xStride,
            float* __restrict__ Out, long oStride, long total4) {
    long idx = (long)blockIdx.x * blockDim.x + threadIdx.x;
    if (idx >= total4) return;
    const int perImg = C * (HW / 4);
    const int n = (int)(idx / perImg);
    const int r = (int)(idx - (long)n * perImg);
    const int c = r / (HW / 4);
    const int p4 = (r - c * (HW / 4)) * 4;
    const float4 ga = *reinterpret_cast<const float4*>(&G[(long)n * gStride + (long)c * HW + p4]);
    const float4 gb = *reinterpret_cast<const float4*>(&G[(long)n * gStride + (long)(c + C) * HW + p4]);
    const float4 xr = *reinterpret_cast<const float4*>(&Xres[(long)n * xStride + (long)c * HW + p4]);
    float4 o;
    o.x = xr.x + ga.x / (1.f + expf(-gb.x));
    o.y = xr.y + ga.y / (1.f + expf(-gb.y));
    o.z = xr.z + ga.z / (1.f + expf(-gb.z));
    o.w = xr.w + ga.w / (1.f + expf(-gb.w));
    *reinterpret_cast<float4*>(&Out[(long)n * oStride + (long)c * HW + p4]) = o;
}

// ---------------- small projection: Out[n, m0..m0+16, hw] = W*X + b ----------------
__global__ void __launch_bounds__(128)
proj16_kernel(const float* __restrict__ X, int Cin,
              const float* __restrict__ W, const float* __restrict__ bias,
              float* __restrict__ Out, int M) {
    __shared__ float sW[16 * 176];
    const int n  = blockIdx.y;
    const int m0 = blockIdx.z * 16;
    const int p  = blockIdx.x * 128 + threadIdx.x;
    for (int i = threadIdx.x; i < 16 * Cin; i += 128) {
        const int o = i / Cin, c = i - o * Cin;
        sW[o * 176 + c] = W[(long)(m0 + o) * Cin + c];
    }
    __syncthreads();
    const float* Xn = X + (long)n * Cin * HW;
    float acc[16];
    #pragma unroll
    for (int o = 0; o < 16; ++o) acc[o] = 0.f;
    #pragma unroll 4
    for (int c = 0; c < Cin; ++c) {
        const float v = Xn[(long)c * HW + p];
        #pragma unroll
        for (int o = 0; o < 16; ++o) acc[o] = fmaf(sW[o * 176 + c], v, acc[o]);
    }
    #pragma unroll
    for (int o = 0; o < 16; ++o)
        Out[((long)n * M + m0 + o) * HW + p] = acc[o] + bias[m0 + o];
}

// ---------------- presoftmax: S[n,q,k] = sum_j K[n,j,k]*Q[n,j,q]  (lower tiles only) ----------------
__global__ void qk_kernel(const float* __restrict__ Kt, const float* __restrict__ Qt,
                          float* __restrict__ S) {
    const int n  = blockIdx.z;
    const int q0 = blockIdx.y * 64;
    const int k0 = blockIdx.x * 64;
    if (k0 > q0) return;
    __shared__ float sK[16][64];
    __shared__ float sQ[16][64];
    const float* Kn = Kt + (long)n * KDIM * HW;
    const float* Qn = Qt + (long)n * KDIM * HW;
    const int p  = threadIdx.x & 63;
    const int jr = threadIdx.x >> 6;
    #pragma unroll
    for (int pass = 0; pass < 4; ++pass) {
        const int j = jr + pass * 4;
        sK[j][p] = Kn[(long)j * HW + k0 + p];
        sQ[j][p] = Qn[(long)j * HW + q0 + p];
    }
    __syncthreads();
    const int tx = threadIdx.x & 15, ty = threadIdx.x >> 4;
    float acc[4][4] = {};
    #pragma unroll
    for (int j = 0; j < 16; ++j) {
        const float4 q4 = *reinterpret_cast<const float4*>(&sQ[j][ty * 4]);
        const float4 k4 = *reinterpret_cast<const float4*>(&sK[j][tx * 4]);
        const float qr[4] = {q4.x, q4.y, q4.z, q4.w};
        const float kr[4] = {k4.x, k4.y, k4.z, k4.w};
        #pragma unroll
        for (int i = 0; i < 4; ++i)
            #pragma unroll
            for (int jj = 0; jj < 4; ++jj)
                acc[i][jj] = fmaf(qr[i], kr[jj], acc[i][jj]);
    }
    float* Sn = S + (long)n * HW * HW;
    #pragma unroll
    for (int i = 0; i < 4; ++i) {
        float4 r = {acc[i][0], acc[i][1], acc[i][2], acc[i][3]};
        *reinterpret_cast<float4*>(&Sn[(long)(q0 + ty * 4 + i) * HW + k0 + tx * 4]) = r;
    }
}

// ---------------- causal softmax per row (faithful semantics) ----------------
__global__ void softmax_kernel(float* __restrict__ S) {
    const int q = blockIdx.x;
    const int n = blockIdx.y;
    float* row = S + ((long)n * HW + (long)q) * HW;
    const int tid = threadIdx.x;  // 256
    __shared__ float red[256];

    float vals[4];
    float lmax = 0.f;
    #pragma unroll
    for (int i = 0; i < 4; ++i) {
        const int k = tid + i * 256;
        const float s = (k < q) ? row[k] : 0.f;
        vals[i] = s;
        if (k < q) lmax = fmaxf(lmax, s);
    }
    red[tid] = lmax;
    __syncthreads();
    for (int s2 = 128; s2 > 0; s2 >>= 1) {
        if (tid < s2) red[tid] = fmaxf(red[tid], red[tid + s2]);
        __syncthreads();
    }
    const float m = red[0];
    __syncthreads();

    float e[4];
    float lsum = 0.f;
    #pragma unroll
    for (int i = 0; i < 4; ++i) {
        const int k = tid + i * 256;
        e[i] = (k < q) ? expf(vals[i] - m) : 0.f;
        lsum += e[i];
    }
    red[tid] = lsum;
    __syncthreads();
    for (int s2 = 128; s2 > 0; s2 >>= 1) {
        if (tid < s2) red[tid] += red[tid + s2];
        __syncthreads();
    }
    const float Skept = red[0];
    const float D = Skept + (float)(HW - q) * expf(-m);
    const float inv = 1.f / (Skept + 1e-7f * D);
    const int kmax = (q & ~63) + 64;
    #pragma unroll
    for (int i = 0; i < 4; ++i) {
        const int k = tid + i * 256;
        if (k < kmax) row[k] = e[i] * inv;
    }
}

// ---------------- AV: Out[n,v,q] = sum_j Att[n,q,j] * V[n,v,j]  (K causally truncated) ----------------
__global__ void av_kernel(const float* __restrict__ Att, const float* __restrict__ V,
                          float* __restrict__ Out) {
    __shared__ float sV[16][80];
    __shared__ float sW[16][64];
    const int n  = blockIdx.y;
    const int q0 = blockIdx.x * 64;
    const float* An = Att + (long)n * HW * HW;
    const float* Vn = V + (long)n * VDIM * HW;
    const int tx = threadIdx.x & 15, ty = threadIdx.x >> 4;
    float acc[5][4] = {};
    const int jmax = min(HW, q0 + 64);

    for (int j0 = 0; j0 < jmax; j0 += 16) {
        for (int i = threadIdx.x; i < 16 * 80; i += 256) {
            const int v = i >> 4, jj = i & 15;
            sV[jj][v] = Vn[(long)v * HW + j0 + jj];
        }
        for (int i = threadIdx.x; i < 16 * 64; i += 256) {
            const int qq = i >> 4, jj = i & 15;
            sW[jj][qq] = An[(long)(q0 + qq) * HW + j0 + jj];
        }
        __syncthreads();
        #pragma unroll
        for (int jj = 0; jj < 16; ++jj) {
            const float4 w4 = *reinterpret_cast<const float4*>(&sW[jj][tx * 4]);
            const float wv[4] = {w4.x, w4.y, w4.z, w4.w};
            #pragma unroll
            for (int i = 0; i < 5; ++i) {
                const float vv = sV[jj][ty * 5 + i];
                #pragma unroll
                for (int j = 0; j < 4; ++j)
                    acc[i][j] = fmaf(vv, wv[j], acc[i][j]);
            }
        }
        __syncthreads();
    }
    #pragma unroll
    for (int i = 0; i < 5; ++i) {
        float4 r = {acc[i][0], acc[i][1], acc[i][2], acc[i][3]};
        *reinterpret_cast<float4*>(&Out[((long)n * VDIM + ty * 5 + i) * HW + q0 + tx * 4]) = r;
    }
}

// ---------------- launcher ----------------
extern "C" void kernel_launch(void* const* d_in, const int* in_sizes, int n_in,
                              void* d_out, int out_size) {
    (void)in_sizes; (void)n_in; (void)out_size;
    const float* x    = (const float*)d_in[0];
    const float* ul   = (const float*)d_in[1];
    const float* b    = (const float*)d_in[2];
    const float* gkWi = (const float*)d_in[3];
    const float* gkbi = (const float*)d_in[4];
    const float* gkWo = (const float*)d_in[5];
    const float* gkbo = (const float*)d_in[6];
    const float* gqWi = (const float*)d_in[7];
    const float* gqbi = (const float*)d_in[8];
    const float* gqWo = (const float*)d_in[9];
    const float* gqbo = (const float*)d_in[10];
    const float* gvWi = (const float*)d_in[11];
    const float* gvbi = (const float*)d_in[12];
    const float* gvWo = (const float*)d_in[13];
    const float* gvbo = (const float*)d_in[14];
    const float* nkW  = (const float*)d_in[15];
    const float* nkb  = (const float*)d_in[16];
    const float* nqW  = (const float*)d_in[17];
    const float* nqb  = (const float*)d_in[18];
    const float* nvW  = (const float*)d_in[19];
    const float* nvb  = (const float*)d_in[20];
    const float* goWi = (const float*)d_in[21];
    const float* gobi = (const float*)d_in[22];
    const float* goWs = (const float*)d_in[23];
    const float* gobs = (const float*)d_in[24];
    const float* goWo = (const float*)d_in[25];
    const float* gobo = (const float*)d_in[26];
    float* out = (float*)d_out;

    float *p_cat, *p_big, *p_gout, *p_keys, *p_quer, *p_vals, *p_att, *p_attv;
    __half *p_bhA, *p_bhQ, *p_bhO, *p_bhH;
    cudaGetSymbolAddress((void**)&p_cat,  g_cat);
    cudaGetSymbolAddress((void**)&p_bhA,  g_bhA);
    cudaGetSymbolAddress((void**)&p_bhQ,  g_bhQ);
    cudaGetSymbolAddress((void**)&p_bhO,  g_bhO);
    cudaGetSymbolAddress((void**)&p_bhH,  g_bhH);
    cudaGetSymbolAddress((void**)&p_big,  g_big);
    cudaGetSymbolAddress((void**)&p_gout, g_gout);
    cudaGetSymbolAddress((void**)&p_keys, g_keys);
    cudaGetSymbolAddress((void**)&p_quer, g_quer);
    cudaGetSymbolAddress((void**)&p_vals, g_vals);
    cudaGetSymbolAddress((void**)&p_att,  g_att);
    cudaGetSymbolAddress((void**)&p_attv, g_attv);

    const long sCat = (long)CKC * HW;
    const long sQ   = (long)CQC * HW;
    const long sO   = (long)COC * HW;
    const long sV   = (long)VDIM * HW;
    const long sBig = (long)2 * CKC * HW;

    {
        const long total = (long)NB * CKC * HW;
        build_cat_h_kernel<<<(unsigned)((total + 255) / 256), 256>>>(x, ul, b, p_cat, p_bhA);
    }
    {   // Q-view pairs (dedicated buffer)
        const long t4 = (long)NB * CQC * (HW / 4);
        celu_pairs4_kernel<<<(unsigned)((t4 + 255) / 256), 256>>>(p_cat + 3 * HW, sCat, CQC, p_bhQ, BHQ_STRIDE);
    }

    const dim3 gridS1(3, NB * 8);    // Cout<=169
    const dim3 gridS2K(6, NB * 8);   // 338
    const dim3 gridS2Q(6, NB * 8);   // 332
    const dim3 gridS2O(5, NB * 8);   // 320

    // ---- GRN-K -> keys ----
    mma_gemm_h2e<<<gridS1, 256>>>(p_bhA, BHA_STRIDE, CKC, gkWi,
                                  nullptr, 0, 0, nullptr, gkbi, nullptr,
                                  CKC, p_bhH, BHH_STRIDE);
    mma_gemm_s2h<<<gridS2K, 256>>>(p_bhH, BHH_STRIDE, CKC, gkWo, gkbo, 2 * CKC, p_big, sBig);
    {
        const long t4 = (long)NB * CKC * (HW / 4);
        gate_kernel<<<(unsigned)((t4 + 255) / 256), 256>>>(p_big, sBig, CKC, p_cat, sCat, p_gout, sCat, t4);
    }
    proj16_kernel<<<dim3(8, NB, 1), 128>>>(p_gout, CKC, nkW, nkb, p_keys, KDIM);

    // ---- GRN-Q -> queries ----
    mma_gemm_h2e<<<gridS1, 256>>>(p_bhQ, BHQ_STRIDE, CQC, gqWi,
                                  nullptr, 0, 0, nullptr, gqbi, nullptr,
                                  CQC, p_bhH, BHH_STRIDE);
    mma_gemm_s2h<<<gridS2Q, 256>>>(p_bhH, BHH_STRIDE, CQC, gqWo, gqbo, 2 * CQC, p_big, sBig);
    {
        const long t4 = (long)NB * CQC * (HW / 4);
        gate_kernel<<<(unsigned)((t4 + 255) / 256), 256>>>(p_big, sBig, CQC, p_cat + 3 * HW, sCat, p_gout, sQ, t4);
    }
    proj16_kernel<<<dim3(8, NB, 1), 128>>>(p_gout, CQC, nqW, nqb, p_quer, KDIM);

    // ---- GRN-V -> values ----
    mma_gemm_h2e<<<gridS1, 256>>>(p_bhA, BHA_STRIDE, CKC, gvWi,
                                  nullptr, 0, 0, nullptr, gvbi, nullptr,
                                  CKC, p_bhH, BHH_STRIDE);
    mma_gemm_s2h<<<gridS2K, 256>>>(p_bhH, BHH_STRIDE, CKC, gvWo, gvbo, 2 * CKC, p_big, sBig);
    {
        const long t4 = (long)NB * CKC * (HW / 4);
        gate_kernel<<<(unsigned)((t4 + 255) / 256), 256>>>(p_big, sBig, CKC, p_cat, sCat, p_gout, sCat, t4);
    }
    proj16_kernel<<<dim3(8, NB, 5), 128>>>(p_gout, CKC, nvW, nvb, p_vals, VDIM);

    // ---- attention ----
    qk_kernel<<<dim3(16, 16, NB), 256>>>(p_keys, p_quer, p_att);
    softmax_kernel<<<dim3(HW, NB), 256>>>(p_att);
    av_kernel<<<dim3(16, NB), 256>>>(p_att, p_vals, p_attv);

    // ---- GRN-O: celu(ul) + celu(attv) pairs -> dual stage-1 -> stage-2 -> gate -> out ----
    {
        const long t4UL = (long)NB * COC * (HW / 4);
        celu_pairs4_kernel<<<(unsigned)((t4UL + 255) / 256), 256>>>(ul, sO, COC, p_bhO, BHO_STRIDE);
        const long t4AV = (long)NB * VDIM * (HW / 4);
        celu_pairs4_kernel<<<(unsigned)((t4AV + 255) / 256), 256>>>(p_attv, sV, VDIM,
                                                                    p_bhO + (long)320 * HW, BHO_STRIDE);
    }
    mma_gemm_h2e<<<gridS1, 256>>>(p_bhO, BHO_STRIDE, COC, goWi,
                                  p_bhO + (long)320 * HW, BHO_STRIDE, VDIM, goWs,
                                  gobi, gobs, COC, p_bhH, BHH_STRIDE);
    mma_gemm_s2h<<<gridS2O, 256>>>(p_bhH, BHH_STRIDE, COC, goWo, gobo, 2 * COC, p_big, sBig);
    {
        const long t4 = (long)NB * COC * (HW / 4);
        gate_kernel<<<(unsigned)((t4 + 255) / 256), 256>>>(p_big, sBig, COC, ul, sO, out, sO, t4);
    }
}

// round 17
// speedup vs baseline: 2.4881x; 1.0913x over previous
#include <cuda_runtime.h>
#include <cuda_fp16.h>
#include <math.h>
#include <stdint.h>

#define NB 32
#define HW 1024

#define CKC 169   // x_ul_b channels
#define CQC 166   // ul_b channels
#define COC 160   // ul channels
#define KDIM 16
#define VDIM 80

#define BHA_ROWS 338
#define BHQ_ROWS 332
#define BHO_ROWS 480
#define BHH_ROWS 344
#define BHA_STRIDE ((long)BHA_ROWS * HW)
#define BHQ_STRIDE ((long)BHQ_ROWS * HW)
#define BHO_STRIDE ((long)BHO_ROWS * HW)
#define BHH_STRIDE ((long)BHH_ROWS * HW)

// ---------------- scratch (static device memory; no allocations) ----------------
__device__ float  g_cat [(size_t)NB * CKC * HW];        // x_ul_b f32 (residuals)
__device__ __half g_bhA [(size_t)NB * BHA_ROWS * HW];   // celu pairs of cat
__device__ __half g_bhQ [(size_t)NB * BHQ_ROWS * HW];   // celu pairs of ul_b view
__device__ __half g_bhO [(size_t)NB * BHO_ROWS * HW];   // celu pairs: ul (0..319), attv (320..479)
__device__ __half g_bhH [(size_t)NB * BHH_ROWS * HW];   // celu pairs of stage-1 hidden
__device__ float  g_big [(size_t)NB * 2 * CKC * HW];    // stage-2 raw [2C, hw]
__device__ float  g_gout[(size_t)NB * CKC * HW];        // GRN output
__device__ float  g_keys[(size_t)NB * KDIM * HW];
__device__ float  g_quer[(size_t)NB * KDIM * HW];
__device__ float  g_vals[(size_t)NB * VDIM * HW];
__device__ float  g_att [(size_t)NB * HW * HW];
__device__ float  g_attv[(size_t)NB * VDIM * HW];

__device__ __forceinline__ float eluf(float v) { return v > 0.f ? v : (expf(v) - 1.f); }

__device__ __forceinline__ void mma_f16(float* d, const unsigned* a, const unsigned* b) {
    asm volatile(
        "mma.sync.aligned.m16n8k16.row.col.f32.f16.f16.f32 "
        "{%0,%1,%2,%3}, {%4,%5,%6,%7}, {%8,%9}, {%0,%1,%2,%3};"
        : "+f"(d[0]), "+f"(d[1]), "+f"(d[2]), "+f"(d[3])
        : "r"(a[0]), "r"(a[1]), "r"(a[2]), "r"(a[3]), "r"(b[0]), "r"(b[1]));
}

// ---------------- concat inputs into [n,169,hw] f32 + celu pairs fp16 ----------------
__global__ void build_cat_h_kernel(const float* __restrict__ x, const float* __restrict__ ul,
                                   const float* __restrict__ b, float* __restrict__ cat,
                                   __half* __restrict__ bh) {
    long idx = (long)blockIdx.x * blockDim.x + threadIdx.x;
    const long total = (long)NB * CKC * HW;
    if (idx >= total) return;
    int p = (int)(idx % HW);
    int c = (int)((idx / HW) % CKC);
    int n = (int)(idx / ((long)CKC * HW));
    float v;
    if (c < 3)        v = x [((long)n * 3   + c        ) * HW + p];
    else if (c < 163) v = ul[((long)n * 160 + (c - 3)  ) * HW + p];
    else              v = b [((long)n * 6   + (c - 163)) * HW + p];
    cat[idx] = v;
    __half* bn = bh + (long)n * BHA_STRIDE;
    bn[(long)c * HW + p]         = __float2half(eluf(v));
    bn[(long)(c + CKC) * HW + p] = __float2half(eluf(-v));
}

// ---------------- celu pairs (vectorized x4): dst[c]=celu(src[c]), dst[c+C]=celu(-src[c]) ----------------
__global__ void __launch_bounds__(256)
celu_pairs4_kernel(const float* __restrict__ src, long srcStride, int C,
                   __half* __restrict__ dst, long dstStride) {
    const long total4 = (long)NB * C * (HW / 4);
    long idx = (long)blockIdx.x * blockDim.x + threadIdx.x;
    if (idx >= total4) return;
    const int perImg = C * (HW / 4);
    const int n = (int)(idx / perImg);
    const int r = (int)(idx - (long)n * perImg);
    const int c = r >> 8;               // HW/4 = 256
    const int p4 = (r & 255) * 4;
    const float4 v = *reinterpret_cast<const float4*>(&src[(long)n * srcStride + (long)c * HW + p4]);
    __half* dn = dst + (long)n * dstStride;
    __half2 hp[2], hm[2];
    hp[0] = __floats2half2_rn(eluf(v.x), eluf(v.y));
    hp[1] = __floats2half2_rn(eluf(v.z), eluf(v.w));
    hm[0] = __floats2half2_rn(eluf(-v.x), eluf(-v.y));
    hm[1] = __floats2half2_rn(eluf(-v.z), eluf(-v.w));
    *reinterpret_cast<uint2*>(&dn[(long)c * HW + p4])       = *reinterpret_cast<uint2*>(hp);
    *reinterpret_cast<uint2*>(&dn[(long)(c + C) * HW + p4]) = *reinterpret_cast<uint2*>(hm);
}

#define SAH 40   // smem stride in halves (80B rows: 16B-aligned, conflict-free bank map 20r mod 32)

// ============ Stage-2 FP16-B GEMM: Out = W*BH + bias ============
#define S2_LOAD_CHUNK(kk)                                                              \
    {                                                                                  \
        const int fb  = (kk) * 32;                                                     \
        const int lim = 2 * Cin;                                                       \
        const int o = o0 + arow;                                                       \
        const bool oOK = o < Cout;                                                     \
        _Pragma("unroll")                                                              \
        for (int jj = 0; jj < 4; ++jj) {                                               \
            const int f = fb + afs + 2 * jj;                                           \
            float2 w2 = {0.f, 0.f};                                                    \
            if (oOK && f < lim)                                                        \
                w2 = *reinterpret_cast<const float2*>(&W[(long)o * lim + f]);          \
            areg[2 * jj] = w2.x; areg[2 * jj + 1] = w2.y;                              \
        }                                                                              \
        const __half* Bn = BH + (long)n * bhStride;                                    \
        _Pragma("unroll")                                                              \
        for (int j = 0; j < 16; ++j) {                                                 \
            const int ff = fb + bf0 + j;                                               \
            hreg[j] = (ff < lim) ? Bn[(long)ff * HW + p0 + bpx]                        \
                                 : __ushort_as_half((unsigned short)0);                \
        }                                                                              \
    }

#define S2_STORE_CHUNK(buf)                                                            \
    {                                                                                  \
        __half* pa = &sA[buf][arow * SAH + afs];                                       \
        _Pragma("unroll")                                                              \
        for (int jj = 0; jj < 4; ++jj)                                                 \
            *reinterpret_cast<__half2*>(pa + 2 * jj) =                                 \
                __floats2half2_rn(areg[2 * jj], areg[2 * jj + 1]);                     \
        __half* pb = &sB[buf][bpx * SAH + bf0];                                        \
        reinterpret_cast<uint4*>(pb)[0] = reinterpret_cast<const uint4*>(hreg)[0];     \
        reinterpret_cast<uint4*>(pb)[1] = reinterpret_cast<const uint4*>(hreg)[1];     \
    }

__global__ void __launch_bounds__(256)
mma_gemm_s2h(const __half* __restrict__ BH, long bhStride, int Cin,
             const float* __restrict__ W, const float* __restrict__ bias,
             int Cout, float* __restrict__ Out, long oStride) {
    __shared__ __align__(16) __half sA[2][64 * SAH];
    __shared__ __align__(16) __half sB[2][128 * SAH];
    const int tid  = threadIdx.x;
    const int warp = tid >> 5;
    const int lane = tid & 31;
    const int n  = blockIdx.y >> 3;
    const int p0 = (blockIdx.y & 7) * 128;
    const int o0 = blockIdx.x * 64;

    const int arow = tid >> 2;
    const int afs  = (tid & 3) * 8;
    const int bpx  = tid & 127;
    const int bf0  = (tid >> 7) * 16;
    const int m0w = (warp & 1) * 32;
    const int n0w = (warp >> 1) * 32;
    const int lq  = lane >> 2;
    const int lr  = lane & 3;

    const int nk = (2 * Cin + 31) >> 5;

    float areg[8];
    __align__(16) __half hreg[16];
    float acc[2][4][4];
    #pragma unroll
    for (int mi = 0; mi < 2; ++mi)
        #pragma unroll
        for (int ni = 0; ni < 4; ++ni)
            #pragma unroll
            for (int e = 0; e < 4; ++e) acc[mi][ni][e] = 0.f;

    S2_LOAD_CHUNK(0);
    S2_STORE_CHUNK(0);
    __syncthreads();

    for (int k = 0; k < nk; ++k) {
        const int buf = k & 1;
        if (k + 1 < nk) S2_LOAD_CHUNK(k + 1);
        #pragma unroll
        for (int ks = 0; ks < 2; ++ks) {
            const int kb = ks * 16 + lr * 2;
            unsigned a[2][4], b[4][2];
            #pragma unroll
            for (int mi = 0; mi < 2; ++mi) {
                const __half* pa = &sA[buf][(m0w + mi * 16 + lq) * SAH + kb];
                a[mi][0] = *reinterpret_cast<const unsigned*>(pa);
                a[mi][1] = *reinterpret_cast<const unsigned*>(pa + 8 * SAH);
                a[mi][2] = *reinterpret_cast<const unsigned*>(pa + 8);
                a[mi][3] = *reinterpret_cast<const unsigned*>(pa + 8 * SAH + 8);
            }
            #pragma unroll
            for (int ni = 0; ni < 4; ++ni) {
                const __half* pb = &sB[buf][(n0w + ni * 8 + lq) * SAH + kb];
                b[ni][0] = *reinterpret_cast<const unsigned*>(pb);
                b[ni][1] = *reinterpret_cast<const unsigned*>(pb + 8);
            }
            #pragma unroll
            for (int mi = 0; mi < 2; ++mi)
                #pragma unroll
                for (int ni = 0; ni < 4; ++ni)
                    mma_f16(acc[mi][ni], a[mi], b[ni]);
        }
        if (k + 1 < nk) S2_STORE_CHUNK((k + 1) & 1);
        __syncthreads();
    }

    #pragma unroll
    for (int mi = 0; mi < 2; ++mi) {
        const int oa = o0 + m0w + mi * 16 + lq;
        const int ob = oa + 8;
        const float ba = (oa < Cout) ? bias[oa] : 0.f;
        const float bb = (ob < Cout) ? bias[ob] : 0.f;
        #pragma unroll
        for (int ni = 0; ni < 4; ++ni) {
            const int pp = p0 + n0w + ni * 8 + 2 * lr;
            if (oa < Cout) {
                float2 r = {acc[mi][ni][0] + ba, acc[mi][ni][1] + ba};
                *reinterpret_cast<float2*>(&Out[(long)n * oStride + (long)oa * HW + pp]) = r;
            }
            if (ob < Cout) {
                float2 r = {acc[mi][ni][2] + bb, acc[mi][ni][3] + bb};
                *reinterpret_cast<float2*>(&Out[(long)n * oStride + (long)ob * HW + pp]) = r;
            }
        }
    }
}

// ============ Stage-1 FP16-B GEMM with celu-pair epilogue ============
#define H2_LOAD_CHUNK(kk)                                                              \
    {                                                                                  \
        const __half* Bs; long bst; int Ci, fb; const float* Ws;                       \
        if ((kk) < nk1) { Bs = BH;  bst = bhStride;  Ci = Cin;  Ws = W;  fb = (kk) * 32; } \
        else            { Bs = BH2; bst = bh2Stride; Ci = Cin2; Ws = W2; fb = ((kk) - nk1) * 32; } \
        const int lim = 2 * Ci;                                                        \
        const int o = o0 + arow;                                                       \
        const bool oOK = o < Cout;                                                     \
        _Pragma("unroll")                                                              \
        for (int jj = 0; jj < 4; ++jj) {                                               \
            const int f = fb + afs + 2 * jj;                                           \
            float2 w2 = {0.f, 0.f};                                                    \
            if (oOK && f < lim)                                                        \
                w2 = *reinterpret_cast<const float2*>(&Ws[(long)o * lim + f]);         \
            areg[2 * jj] = w2.x; areg[2 * jj + 1] = w2.y;                              \
        }                                                                              \
        const __half* Bn = Bs + (long)n * bst;                                         \
        _Pragma("unroll")                                                              \
        for (int j = 0; j < 16; ++j) {                                                 \
            const int ff = fb + bf0 + j;                                               \
            hreg[j] = (ff < lim) ? Bn[(long)ff * HW + p0 + bpx]                        \
                                 : __ushort_as_half((unsigned short)0);                \
        }                                                                              \
    }

__global__ void __launch_bounds__(256)
mma_gemm_h2e(const __half* __restrict__ BH, long bhStride, int Cin,
             const float* __restrict__ W,
             const __half* __restrict__ BH2, long bh2Stride, int Cin2,
             const float* __restrict__ W2,
             const float* __restrict__ bias, const float* __restrict__ bias2,
             int Cout, __half* __restrict__ OutH, long oStrideH) {
    __shared__ __align__(16) __half sA[2][64 * SAH];
    __shared__ __align__(16) __half sB[2][128 * SAH];
    const int tid  = threadIdx.x;
    const int warp = tid >> 5;
    const int lane = tid & 31;
    const int n  = blockIdx.y >> 3;
    const int p0 = (blockIdx.y & 7) * 128;
    const int o0 = blockIdx.x * 64;

    const int arow = tid >> 2;
    const int afs  = (tid & 3) * 8;
    const int bpx  = tid & 127;
    const int bf0  = (tid >> 7) * 16;
    const int m0w = (warp & 1) * 32;
    const int n0w = (warp >> 1) * 32;
    const int lq  = lane >> 2;
    const int lr  = lane & 3;

    const int nk1 = (2 * Cin + 31) >> 5;
    const int nk2 = W2 ? ((2 * Cin2 + 31) >> 5) : 0;
    const int nk  = nk1 + nk2;

    float areg[8];
    __align__(16) __half hreg[16];
    float acc[2][4][4];
    #pragma unroll
    for (int mi = 0; mi < 2; ++mi)
        #pragma unroll
        for (int ni = 0; ni < 4; ++ni)
            #pragma unroll
            for (int e = 0; e < 4; ++e) acc[mi][ni][e] = 0.f;

    H2_LOAD_CHUNK(0);
    S2_STORE_CHUNK(0);
    __syncthreads();

    for (int k = 0; k < nk; ++k) {
        const int buf = k & 1;
        if (k + 1 < nk) H2_LOAD_CHUNK(k + 1);
        #pragma unroll
        for (int ks = 0; ks < 2; ++ks) {
            const int kb = ks * 16 + lr * 2;
            unsigned a[2][4], b[4][2];
            #pragma unroll
            for (int mi = 0; mi < 2; ++mi) {
                const __half* pa = &sA[buf][(m0w + mi * 16 + lq) * SAH + kb];
                a[mi][0] = *reinterpret_cast<const unsigned*>(pa);
                a[mi][1] = *reinterpret_cast<const unsigned*>(pa + 8 * SAH);
                a[mi][2] = *reinterpret_cast<const unsigned*>(pa + 8);
                a[mi][3] = *reinterpret_cast<const unsigned*>(pa + 8 * SAH + 8);
            }
            #pragma unroll
            for (int ni = 0; ni < 4; ++ni) {
                const __half* pb = &sB[buf][(n0w + ni * 8 + lq) * SAH + kb];
                b[ni][0] = *reinterpret_cast<const unsigned*>(pb);
                b[ni][1] = *reinterpret_cast<const unsigned*>(pb + 8);
            }
            #pragma unroll
            for (int mi = 0; mi < 2; ++mi)
                #pragma unroll
                for (int ni = 0; ni < 4; ++ni)
                    mma_f16(acc[mi][ni], a[mi], b[ni]);
        }
        if (k + 1 < nk) S2_STORE_CHUNK((k + 1) & 1);
        __syncthreads();
    }

    // epilogue: write celu pairs (rows o and o+Cout) as fp16
    __half* dn = OutH + (long)n * oStrideH;
    #pragma unroll
    for (int mi = 0; mi < 2; ++mi) {
        const int oa = o0 + m0w + mi * 16 + lq;
        const int ob = oa + 8;
        const float ba = (oa < Cout) ? (bias[oa] + (bias2 ? bias2[oa] : 0.f)) : 0.f;
        const float bb = (ob < Cout) ? (bias[ob] + (bias2 ? bias2[ob] : 0.f)) : 0.f;
        #pragma unroll
        for (int ni = 0; ni < 4; ++ni) {
            const int pp = p0 + n0w + ni * 8 + 2 * lr;
            if (oa < Cout) {
                const float v0 = acc[mi][ni][0] + ba, v1 = acc[mi][ni][1] + ba;
                *reinterpret_cast<__half2*>(&dn[(long)oa * HW + pp]) =
                    __floats2half2_rn(eluf(v0), eluf(v1));
                *reinterpret_cast<__half2*>(&dn[(long)(oa + Cout) * HW + pp]) =
                    __floats2half2_rn(eluf(-v0), eluf(-v1));
            }
            if (ob < Cout) {
                const float v0 = acc[mi][ni][2] + bb, v1 = acc[mi][ni][3] + bb;
                *reinterpret_cast<__half2*>(&dn[(long)ob * HW + pp]) =
                    __floats2half2_rn(eluf(v0), eluf(v1));
                *reinterpret_cast<__half2*>(&dn[(long)(ob + Cout) * HW + pp]) =
                    __floats2half2_rn(eluf(-v0), eluf(-v1));
            }
        }
    }
}

// ---------------- gate: out = Xres + ga*sigmoid(gb), ga=G[c], gb=G[c+C] ----------------
__global__ void __launch_bounds__(256)
gate_kernel(const float* __restrict__ G, long gStride, int C,
            const float* __restrict__ Xres, long xStride,
            float* __restrict__ Out, long oStride, long total4) {
    long idx = (long)blockIdx.x * blockDim.x + threadIdx.x;
    if (idx >= total4) return;
    const int perImg = C * (HW / 4);
    const int n = (int)(idx / perImg);
    const int r = (int)(idx - (long)n * perImg);
    const int c = r / (HW / 4);
    const int p4 = (r - c * (HW / 4)) * 4;
    const float4 ga = *reinterpret_cast<const float4*>(&G[(long)n * gStride + (long)c * HW + p4]);
    const float4 gb = *reinterpret_cast<const float4*>(&G[(long)n * gStride + (long)(c + C) * HW + p4]);
    const float4 xr = *reinterpret_cast<const float4*>(&Xres[(long)n * xStride + (long)c * HW + p4]);
    float4 o;
    o.x = xr.x + ga.x / (1.f + expf(-gb.x));
    o.y = xr.y + ga.y / (1.f + expf(-gb.y));
    o.z = xr.z + ga.z / (1.f + expf(-gb.z));
    o.w = xr.w + ga.w / (1.f + expf(-gb.w));
    *reinterpret_cast<float4*>(&Out[(long)n * oStride + (long)c * HW + p4]) = o;
}

// ---------------- small projection: Out[n, m0..m0+16, hw] = W*X + b ----------------
__global__ void __launch_bounds__(128)
proj16_kernel(const float* __restrict__ X, int Cin,
              const float* __restrict__ W, const float* __restrict__ bias,
              float* __restrict__ Out, int M) {
    __shared__ float sW[16 * 176];
    const int n  = blockIdx.y;
    const int m0 = blockIdx.z * 16;
    const int p  = blockIdx.x * 128 + threadIdx.x;
    for (int i = threadIdx.x; i < 16 * Cin; i += 128) {
        const int o = i / Cin, c = i - o * Cin;
        sW[o * 176 + c] = W[(long)(m0 + o) * Cin + c];
    }
    __syncthreads();
    const float* Xn = X + (long)n * Cin * HW;
    float acc[16];
    #pragma unroll
    for (int o = 0; o < 16; ++o) acc[o] = 0.f;
    #pragma unroll 4
    for (int c = 0; c < Cin; ++c) {
        const float v = Xn[(long)c * HW + p];
        #pragma unroll
        for (int o = 0; o < 16; ++o) acc[o] = fmaf(sW[o * 176 + c], v, acc[o]);
    }
    #pragma unroll
    for (int o = 0; o < 16; ++o)
        Out[((long)n * M + m0 + o) * HW + p] = acc[o] + bias[m0 + o];
}

// ---------------- presoftmax: S[n,q,k] = sum_j K[n,j,k]*Q[n,j,q]  (lower tiles only) ----------------
__global__ void qk_kernel(const float* __restrict__ Kt, const float* __restrict__ Qt,
                          float* __restrict__ S) {
    const int n  = blockIdx.z;
    const int q0 = blockIdx.y * 64;
    const int k0 = blockIdx.x * 64;
    if (k0 > q0) return;
    __shared__ float sK[16][64];
    __shared__ float sQ[16][64];
    const float* Kn = Kt + (long)n * KDIM * HW;
    const float* Qn = Qt + (long)n * KDIM * HW;
    const int p  = threadIdx.x & 63;
    const int jr = threadIdx.x >> 6;
    #pragma unroll
    for (int pass = 0; pass < 4; ++pass) {
        const int j = jr + pass * 4;
        sK[j][p] = Kn[(long)j * HW + k0 + p];
        sQ[j][p] = Qn[(long)j * HW + q0 + p];
    }
    __syncthreads();
    const int tx = threadIdx.x & 15, ty = threadIdx.x >> 4;
    float acc[4][4] = {};
    #pragma unroll
    for (int j = 0; j < 16; ++j) {
        const float4 q4 = *reinterpret_cast<const float4*>(&sQ[j][ty * 4]);
        const float4 k4 = *reinterpret_cast<const float4*>(&sK[j][tx * 4]);
        const float qr[4] = {q4.x, q4.y, q4.z, q4.w};
        const float kr[4] = {k4.x, k4.y, k4.z, k4.w};
        #pragma unroll
        for (int i = 0; i < 4; ++i)
            #pragma unroll
            for (int jj = 0; jj < 4; ++jj)
                acc[i][jj] = fmaf(qr[i], kr[jj], acc[i][jj]);
    }
    float* Sn = S + (long)n * HW * HW;
    #pragma unroll
    for (int i = 0; i < 4; ++i) {
        float4 r = {acc[i][0], acc[i][1], acc[i][2], acc[i][3]};
        *reinterpret_cast<float4*>(&Sn[(long)(q0 + ty * 4 + i) * HW + k0 + tx * 4]) = r;
    }
}

// ---------------- causal softmax per row (faithful semantics) ----------------
__global__ void softmax_kernel(float* __restrict__ S) {
    const int q = blockIdx.x;
    const int n = blockIdx.y;
    float* row = S + ((long)n * HW + (long)q) * HW;
    const int tid = threadIdx.x;  // 256
    __shared__ float red[256];

    float vals[4];
    float lmax = 0.f;
    #pragma unroll
    for (int i = 0; i < 4; ++i) {
        const int k = tid + i * 256;
        const float s = (k < q) ? row[k] : 0.f;
        vals[i] = s;
        if (k < q) lmax = fmaxf(lmax, s);
    }
    red[tid] = lmax;
    __syncthreads();
    for (int s2 = 128; s2 > 0; s2 >>= 1) {
        if (tid < s2) red[tid] = fmaxf(red[tid], red[tid + s2]);
        __syncthreads();
    }
    const float m = red[0];
    __syncthreads();

    float e[4];
    float lsum = 0.f;
    #pragma unroll
    for (int i = 0; i < 4; ++i) {
        const int k = tid + i * 256;
        e[i] = (k < q) ? expf(vals[i] - m) : 0.f;
        lsum += e[i];
    }
    red[tid] = lsum;
    __syncthreads();
    for (int s2 = 128; s2 > 0; s2 >>= 1) {
        if (tid < s2) red[tid] += red[tid + s2];
        __syncthreads();
    }
    const float Skept = red[0];
    const float D = Skept + (float)(HW - q) * expf(-m);
    const float inv = 1.f / (Skept + 1e-7f * D);
    const int kmax = (q & ~63) + 64;
    #pragma unroll
    for (int i = 0; i < 4; ++i) {
        const int k = tid + i * 256;
        if (k < kmax) row[k] = e[i] * inv;
    }
}

// ---------------- AV: Out[n,v,q] = sum_j Att[n,q,j] * V[n,v,j]  (K causally truncated) ----------------
__global__ void av_kernel(const float* __restrict__ Att, const float* __restrict__ V,
                          float* __restrict__ Out) {
    __shared__ float sV[16][80];
    __shared__ float sW[16][64];
    const int n  = blockIdx.y;
    const int q0 = blockIdx.x * 64;
    const float* An = Att + (long)n * HW * HW;
    const float* Vn = V + (long)n * VDIM * HW;
    const int tx = threadIdx.x & 15, ty = threadIdx.x >> 4;
    float acc[5][4] = {};
    const int jmax = min(HW, q0 + 64);

    for (int j0 = 0; j0 < jmax; j0 += 16) {
        for (int i = threadIdx.x; i < 16 * 80; i += 256) {
            const int v = i >> 4, jj = i & 15;
            sV[jj][v] = Vn[(long)v * HW + j0 + jj];
        }
        for (int i = threadIdx.x; i < 16 * 64; i += 256) {
            const int qq = i >> 4, jj = i & 15;
            sW[jj][qq] = An[(long)(q0 + qq) * HW + j0 + jj];
        }
        __syncthreads();
        #pragma unroll
        for (int jj = 0; jj < 16; ++jj) {
            const float4 w4 = *reinterpret_cast<const float4*>(&sW[jj][tx * 4]);
            const float wv[4] = {w4.x, w4.y, w4.z, w4.w};
            #pragma unroll
            for (int i = 0; i < 5; ++i) {
                const float vv = sV[jj][ty * 5 + i];
                #pragma unroll
                for (int j = 0; j < 4; ++j)
                    acc[i][j] = fmaf(vv, wv[j], acc[i][j]);
            }
        }
        __syncthreads();
    }
    #pragma unroll
    for (int i = 0; i < 5; ++i) {
        float4 r = {acc[i][0], acc[i][1], acc[i][2], acc[i][3]};
        *reinterpret_cast<float4*>(&Out[((long)n * VDIM + ty * 5 + i) * HW + q0 + tx * 4]) = r;
    }
}

// ---------------- launcher ----------------
extern "C" void kernel_launch(void* const* d_in, const int* in_sizes, int n_in,
                              void* d_out, int out_size) {
    (void)in_sizes; (void)n_in; (void)out_size;
    const float* x    = (const float*)d_in[0];
    const float* ul   = (const float*)d_in[1];
    const float* b    = (const float*)d_in[2];
    const float* gkWi = (const float*)d_in[3];
    const float* gkbi = (const float*)d_in[4];
    const float* gkWo = (const float*)d_in[5];
    const float* gkbo = (const float*)d_in[6];
    const float* gqWi = (const float*)d_in[7];
    const float* gqbi = (const float*)d_in[8];
    const float* gqWo = (const float*)d_in[9];
    const float* gqbo = (const float*)d_in[10];
    const float* gvWi = (const float*)d_in[11];
    const float* gvbi = (const float*)d_in[12];
    const float* gvWo = (const float*)d_in[13];
    const float* gvbo = (const float*)d_in[14];
    const float* nkW  = (const float*)d_in[15];
    const float* nkb  = (const float*)d_in[16];
    const float* nqW  = (const float*)d_in[17];
    const float* nqb  = (const float*)d_in[18];
    const float* nvW  = (const float*)d_in[19];
    const float* nvb  = (const float*)d_in[20];
    const float* goWi = (const float*)d_in[21];
    const float* gobi = (const float*)d_in[22];
    const float* goWs = (const float*)d_in[23];
    const float* gobs = (const float*)d_in[24];
    const float* goWo = (const float*)d_in[25];
    const float* gobo = (const float*)d_in[26];
    float* out = (float*)d_out;

    float *p_cat, *p_big, *p_gout, *p_keys, *p_quer, *p_vals, *p_att, *p_attv;
    __half *p_bhA, *p_bhQ, *p_bhO, *p_bhH;
    cudaGetSymbolAddress((void**)&p_cat,  g_cat);
    cudaGetSymbolAddress((void**)&p_bhA,  g_bhA);
    cudaGetSymbolAddress((void**)&p_bhQ,  g_bhQ);
    cudaGetSymbolAddress((void**)&p_bhO,  g_bhO);
    cudaGetSymbolAddress((void**)&p_bhH,  g_bhH);
    cudaGetSymbolAddress((void**)&p_big,  g_big);
    cudaGetSymbolAddress((void**)&p_gout, g_gout);
    cudaGetSymbolAddress((void**)&p_keys, g_keys);
    cudaGetSymbolAddress((void**)&p_quer, g_quer);
    cudaGetSymbolAddress((void**)&p_vals, g_vals);
    cudaGetSymbolAddress((void**)&p_att,  g_att);
    cudaGetSymbolAddress((void**)&p_attv, g_attv);

    const long sCat = (long)CKC * HW;
    const long sQ   = (long)CQC * HW;
    const long sO   = (long)COC * HW;
    const long sV   = (long)VDIM * HW;
    const long sBig = (long)2 * CKC * HW;

    {
        const long total = (long)NB * CKC * HW;
        build_cat_h_kernel<<<(unsigned)((total + 255) / 256), 256>>>(x, ul, b, p_cat, p_bhA);
    }
    {   // Q-view pairs (dedicated buffer)
        const long t4 = (long)NB * CQC * (HW / 4);
        celu_pairs4_kernel<<<(unsigned)((t4 + 255) / 256), 256>>>(p_cat + 3 * HW, sCat, CQC, p_bhQ, BHQ_STRIDE);
    }

    const dim3 gridS1(3, NB * 8);    // Cout<=169
    const dim3 gridS2K(6, NB * 8);   // 338
    const dim3 gridS2Q(6, NB * 8);   // 332
    const dim3 gridS2O(5, NB * 8);   // 320

    // ---- GRN-K -> keys ----
    mma_gemm_h2e<<<gridS1, 256>>>(p_bhA, BHA_STRIDE, CKC, gkWi,
                                  nullptr, 0, 0, nullptr, gkbi, nullptr,
                                  CKC, p_bhH, BHH_STRIDE);
    mma_gemm_s2h<<<gridS2K, 256>>>(p_bhH, BHH_STRIDE, CKC, gkWo, gkbo, 2 * CKC, p_big, sBig);
    {
        const long t4 = (long)NB * CKC * (HW / 4);
        gate_kernel<<<(unsigned)((t4 + 255) / 256), 256>>>(p_big, sBig, CKC, p_cat, sCat, p_gout, sCat, t4);
    }
    proj16_kernel<<<dim3(8, NB, 1), 128>>>(p_gout, CKC, nkW, nkb, p_keys, KDIM);

    // ---- GRN-Q -> queries ----
    mma_gemm_h2e<<<gridS1, 256>>>(p_bhQ, BHQ_STRIDE, CQC, gqWi,
                                  nullptr, 0, 0, nullptr, gqbi, nullptr,
                                  CQC, p_bhH, BHH_STRIDE);
    mma_gemm_s2h<<<gridS2Q, 256>>>(p_bhH, BHH_STRIDE, CQC, gqWo, gqbo, 2 * CQC, p_big, sBig);
    {
        const long t4 = (long)NB * CQC * (HW / 4);
        gate_kernel<<<(unsigned)((t4 + 255) / 256), 256>>>(p_big, sBig, CQC, p_cat + 3 * HW, sCat, p_gout, sQ, t4);
    }
    proj16_kernel<<<dim3(8, NB, 1), 128>>>(p_gout, CQC, nqW, nqb, p_quer, KDIM);

    // ---- GRN-V -> values ----
    mma_gemm_h2e<<<gridS1, 256>>>(p_bhA, BHA_STRIDE, CKC, gvWi,
                                  nullptr, 0, 0, nullptr, gvbi, nullptr,
                                  CKC, p_bhH, BHH_STRIDE);
    mma_gemm_s2h<<<gridS2K, 256>>>(p_bhH, BHH_STRIDE, CKC, gvWo, gvbo, 2 * CKC, p_big, sBig);
    {
        const long t4 = (long)NB * CKC * (HW / 4);
        gate_kernel<<<(unsigned)((t4 + 255) / 256), 256>>>(p_big, sBig, CKC, p_cat, sCat, p_gout, sCat, t4);
    }
    proj16_kernel<<<dim3(8, NB, 5), 128>>>(p_gout, CKC, nvW, nvb, p_vals, VDIM);

    // ---- attention ----
    qk_kernel<<<dim3(16, 16, NB), 256>>>(p_keys, p_quer, p_att);
    softmax_kernel<<<dim3(HW, NB), 256>>>(p_att);
    av_kernel<<<dim3(16, NB), 256>>>(p_att, p_vals, p_attv);

    // ---- GRN-O: celu(ul) + celu(attv) pairs -> dual stage-1 -> stage-2 -> gate -> out ----
    {
        const long t4UL = (long)NB * COC * (HW / 4);
        celu_pairs4_kernel<<<(unsigned)((t4UL + 255) / 256), 256>>>(ul, sO, COC, p_bhO, BHO_STRIDE);
        const long t4AV = (long)NB * VDIM * (HW / 4);
        celu_pairs4_kernel<<<(unsigned)((t4AV + 255) / 256), 256>>>(p_attv, sV, VDIM,
                                                                    p_bhO + (long)320 * HW, BHO_STRIDE);
    }
    mma_gemm_h2e<<<gridS1, 256>>>(p_bhO, BHO_STRIDE, COC, goWi,
                                  p_bhO + (long)320 * HW, BHO_STRIDE, VDIM, goWs,
                                  gobi, gobs, COC, p_bhH, BHH_STRIDE);
    mma_gemm_s2h<<<gridS2O, 256>>>(p_bhH, BHH_STRIDE, COC, goWo, gobo, 2 * COC, p_big, sBig);
    {
        const long t4 = (long)NB * COC * (HW / 4);
        gate_kernel<<<(unsigned)((t4 + 255) / 256), 256>>>(p_big, sBig, COC, ul, sO, out, sO, t4);
    }
}